// round 6
// baseline (speedup 1.0000x reference)
#include <cuda_runtime.h>
#include <cstdio>

#define BATCH 2
#define NPTS  4096
#define KNN   20
#define BN_   (BATCH*NPTS)        // 8192
#define CNT_EDGE (float)(BATCH*NPTS*KNN)   // 163840
#define EPSV 1e-5f
#define SLOPE 0.2f
#define TOPK_CAP 1024

// ---------------- static scratch (no runtime alloc allowed) ----------------
__device__ float g_xb[BN_*3];
__device__ float g_x1[BN_*64];
__device__ float g_x2[BN_*64];
__device__ float g_x3[BN_*128];
__device__ float g_x4[BN_*256];
__device__ float g_sq[BN_];
__device__ float g_D[(size_t)BATCH*NPTS*NPTS];   // 134MB distance scratch
__device__ int   g_idx[BN_*KNN];
__device__ float g_u[BN_*256];
__device__ float g_v[BN_*256];
__device__ float g_wdiff[256*256];
__device__ float g_h[(size_t)BN_*1024];
__device__ float g_ps [(size_t)BN_*256];  // partial sums
__device__ float g_pss[(size_t)BN_*256];  // partial sumsq
__device__ float g_sums[1024];
__device__ float g_sumsq[1024];

// ---------------- kernels ----------------

// x (B,3,N) -> g_xb (B,N,3)
__global__ void k_transpose_x(const float* __restrict__ x) {
    int i = blockIdx.x*blockDim.x + threadIdx.x;
    if (i >= BN_) return;
    int b = i / NPTS, n = i % NPTS;
    #pragma unroll
    for (int c = 0; c < 3; c++)
        g_xb[(size_t)i*3 + c] = x[((size_t)b*3 + c)*NPTS + n];
}

// squared norms per row
__global__ void k_sqnorm(const float* __restrict__ F, int C) {
    int i = blockIdx.x*blockDim.x + threadIdx.x;
    if (i >= BN_) return;
    const float* r = F + (size_t)i*C;
    float s = 0.f;
    for (int c = 0; c < C; c++) s += r[c]*r[c];
    g_sq[i] = s;
}

// D[b][n][m] = 2*<x_n,x_m> - ||x_n||^2 - ||x_m||^2
// Tiles: 256 n-rows (by) x 128 m-cols (bx), 16x8 micro, double-buffered.
// Triangle scheme: skip if bx < 2by; compute if bx >= 2by; mirror if bx >= 2by+2.
__global__ void __launch_bounds__(256, 1)
k_dist_sym2(const float* __restrict__ F, int C) {
    int bx = blockIdx.x, by = blockIdx.y;
    if (bx < 2*by) return;            // lower tile: covered by a mirror
    int b = blockIdx.z;
    const float* Fb = F + (size_t)b*NPTS*C;
    int m0 = bx*128, n0 = by*256;

    __shared__ float As[2][8][260];   // [k][n-row]; reused as mirror staging
    __shared__ float Bs[2][8][132];   // [k][m-row]

    int tid = threadIdx.x;
    int wrow = tid >> 1, wh = (tid & 1) * 4;

    float acc[16][8];
    #pragma unroll
    for (int i = 0; i < 16; i++)
        #pragma unroll
        for (int j = 0; j < 8; j++) acc[i][j] = 0.f;

    int nIter = (C + 7) / 8;
    bool vec = (C % 8 == 0);

    // prologue (buffer 0)
    if (vec) {
        float4 a0 = *(const float4*)&Fb[(size_t)(n0+tid)*C + 0];
        float4 a1 = *(const float4*)&Fb[(size_t)(n0+tid)*C + 4];
        As[0][0][tid] = a0.x; As[0][1][tid] = a0.y;
        As[0][2][tid] = a0.z; As[0][3][tid] = a0.w;
        As[0][4][tid] = a1.x; As[0][5][tid] = a1.y;
        As[0][6][tid] = a1.z; As[0][7][tid] = a1.w;
        float4 bv = *(const float4*)&Fb[(size_t)(m0+wrow)*C + wh];
        Bs[0][wh+0][wrow] = bv.x; Bs[0][wh+1][wrow] = bv.y;
        Bs[0][wh+2][wrow] = bv.z; Bs[0][wh+3][wrow] = bv.w;
    } else {
        #pragma unroll
        for (int q = 0; q < 8; q++)
            As[0][q][tid] = (q < C) ? Fb[(size_t)(n0+tid)*C + q] : 0.f;
        #pragma unroll
        for (int q = 0; q < 4; q++) {
            int kk = wh + q;
            Bs[0][kk][wrow] = (kk < C) ? Fb[(size_t)(m0+wrow)*C + kk] : 0.f;
        }
    }
    __syncthreads();

    int ti = tid & 15, tj = tid >> 4;   // ti -> m (8 each), tj -> n (16 each)
    for (int it = 0; it < nIter; it++) {
        int cur = it & 1, nxt = cur ^ 1;
        if (it + 1 < nIter) {
            int c0 = (it + 1) * 8;
            float4 a0 = *(const float4*)&Fb[(size_t)(n0+tid)*C + c0 + 0];
            float4 a1 = *(const float4*)&Fb[(size_t)(n0+tid)*C + c0 + 4];
            As[nxt][0][tid] = a0.x; As[nxt][1][tid] = a0.y;
            As[nxt][2][tid] = a0.z; As[nxt][3][tid] = a0.w;
            As[nxt][4][tid] = a1.x; As[nxt][5][tid] = a1.y;
            As[nxt][6][tid] = a1.z; As[nxt][7][tid] = a1.w;
            float4 bv = *(const float4*)&Fb[(size_t)(m0+wrow)*C + c0 + wh];
            Bs[nxt][wh+0][wrow] = bv.x; Bs[nxt][wh+1][wrow] = bv.y;
            Bs[nxt][wh+2][wrow] = bv.z; Bs[nxt][wh+3][wrow] = bv.w;
        }
        #pragma unroll
        for (int k = 0; k < 8; k++) {
            float a[16], bv[8];
            #pragma unroll
            for (int u = 0; u < 16; u++) a[u] = As[cur][k][tj*16 + u];
            #pragma unroll
            for (int u = 0; u < 8; u++)  bv[u] = Bs[cur][k][ti*8 + u];
            #pragma unroll
            for (int i = 0; i < 16; i++)
                #pragma unroll
                for (int j = 0; j < 8; j++) acc[i][j] += a[i]*bv[j];
        }
        __syncthreads();
    }

    // finalize distances in-register
    float sqm[8];
    #pragma unroll
    for (int j = 0; j < 8; j++) sqm[j] = g_sq[b*NPTS + m0 + ti*8 + j];
    #pragma unroll
    for (int i = 0; i < 16; i++) {
        float sqn = g_sq[b*NPTS + n0 + tj*16 + i];
        #pragma unroll
        for (int j = 0; j < 8; j++)
            acc[i][j] = 2.f*acc[i][j] - sqn - sqm[j];
    }

    // write normal tile: D[n][m]
    #pragma unroll
    for (int i = 0; i < 16; i++) {
        int n = n0 + tj*16 + i;
        float* orow = &g_D[((size_t)b*NPTS + n)*NPTS + m0 + ti*8];
        float4 v0 = make_float4(acc[i][0], acc[i][1], acc[i][2], acc[i][3]);
        float4 v1 = make_float4(acc[i][4], acc[i][5], acc[i][6], acc[i][7]);
        *(float4*)&orow[0] = v0;
        *(float4*)&orow[4] = v1;
    }

    // mirror: D[m][n] for strictly-upper tiles, staged through smem (coalesced)
    if (bx >= 2*by + 2) {
        float* st = &As[0][0][0];           // 16 x 260 staging (4160 floats)
        for (int cc = 0; cc < 8; cc++) {    // 8 chunks of 16 m-cols
            __syncthreads();
            if ((ti >> 1) == cc) {
                int rbase = (ti & 1) * 8;
                #pragma unroll
                for (int j = 0; j < 8; j++)
                    #pragma unroll
                    for (int i = 0; i < 16; i++)
                        st[(rbase + j)*260 + tj*16 + i] = acc[i][j];
            }
            __syncthreads();
            int rr = tid >> 4;              // 0..15: m-row within chunk
            int c0w = (tid & 15) * 16;      // 0..240: n-col start
            int m = m0 + cc*16 + rr;
            float* dst = &g_D[((size_t)b*NPTS + m)*NPTS + n0 + c0w];
            #pragma unroll
            for (int q = 0; q < 4; q++)
                *(float4*)&dst[q*4] = *(float4*)&st[rr*260 + c0w + q*4];
        }
    }
}

__device__ __forceinline__ unsigned f2ord(float f) {
    unsigned u = __float_as_uint(f);
    return (u & 0x80000000u) ? ~u : (u | 0x80000000u);
}

// top-20 (largest values, tie -> lowest index) per distance row.
// Radix-select: single global pass, 11-bit histogram, candidate ranking.
__global__ void k_topk() {
    __shared__ unsigned hist[2048];
    __shared__ unsigned tsum[256];
    __shared__ int sh_bin, ccnt;
    __shared__ unsigned long long cand[TOPK_CAP];

    int bn = blockIdx.x;
    int tid = threadIdx.x;
    const float4* rowv = (const float4*)&g_D[(size_t)bn*NPTS];

    for (int i = tid; i < 2048; i += 256) hist[i] = 0;
    if (tid == 0) ccnt = 0;
    __syncthreads();

    // load 16 values/thread, compute ordered keys, histogram top-11 bits
    unsigned ord[16];
    #pragma unroll
    for (int q = 0; q < 4; q++) {
        float4 v = rowv[tid + q*256];
        ord[q*4+0] = f2ord(v.x);
        ord[q*4+1] = f2ord(v.y);
        ord[q*4+2] = f2ord(v.z);
        ord[q*4+3] = f2ord(v.w);
    }
    #pragma unroll
    for (int q = 0; q < 16; q++) atomicAdd(&hist[ord[q] >> 21], 1u);
    __syncthreads();

    // per-thread sum over its 8 bins, then suffix-scan across threads
    unsigned s_local = 0;
    #pragma unroll
    for (int j = 0; j < 8; j++) s_local += hist[tid*8 + j];
    tsum[tid] = s_local;
    __syncthreads();
    for (int off = 1; off < 256; off <<= 1) {
        unsigned add = (tid + off < 256) ? tsum[tid + off] : 0u;
        __syncthreads();
        tsum[tid] += add;
        __syncthreads();
    }
    // tsum[tid] = sum over bins of threads >= tid
    unsigned cum = tsum[tid] - s_local;   // count strictly above this thread's bin range
    for (int j = 7; j >= 0; j--) {
        unsigned c = hist[tid*8 + j];
        if (cum < KNN && cum + c >= KNN) { sh_bin = tid*8 + j; }
        cum += c;
    }
    __syncthreads();

    int thr = sh_bin;
    // collect candidates: all elements with bin >= threshold bin
    #pragma unroll
    for (int q = 0; q < 16; q++) {
        if ((int)(ord[q] >> 21) >= thr) {
            int idx = 4*(tid + (q >> 2)*256) + (q & 3);
            int p = atomicAdd(&ccnt, 1);
            if (p < TOPK_CAP)
                cand[p] = ((unsigned long long)ord[q] << 32) | (unsigned)(NPTS - 1 - idx);
        }
    }
    __syncthreads();

    int T = ccnt;
    if (T <= TOPK_CAP) {
        // rank candidates; keys are unique (index embedded) -> deterministic
        for (int i = tid; i < T; i += 256) {
            unsigned long long ki = cand[i];
            int r = 0;
            for (int j = 0; j < T; j++) r += (cand[j] > ki);
            if (r < KNN) {
                int idx = (NPTS - 1) - (int)(unsigned)(ki & 0xFFFFFFFFull);
                g_idx[bn*KNN + r] = idx;
            }
        }
    } else {
        // fallback (degenerate): iterative in-register selection, always correct
        __shared__ unsigned long long rb[256];
        unsigned mask = 0xFFFFu;
        for (int it = 0; it < KNN; it++) {
            unsigned long long best = 0ull;
            #pragma unroll
            for (int q = 0; q < 16; q++) {
                if ((mask >> q) & 1u) {
                    int idx = 4*(tid + (q >> 2)*256) + (q & 3);
                    unsigned long long k = ((unsigned long long)ord[q] << 32)
                                         | (unsigned)(NPTS - 1 - idx);
                    if (k > best) best = k;
                }
            }
            rb[tid] = best;
            __syncthreads();
            for (int st = 128; st > 0; st >>= 1) {
                if (tid < st && rb[tid + st] > rb[tid]) rb[tid] = rb[tid + st];
                __syncthreads();
            }
            unsigned long long win = rb[0];
            if (tid == 0)
                g_idx[bn*KNN + it] = (NPTS - 1) - (int)(unsigned)(win & 0xFFFFFFFFull);
            // owner clears its bit
            #pragma unroll
            for (int q = 0; q < 16; q++) {
                if ((mask >> q) & 1u) {
                    int idx = 4*(tid + (q >> 2)*256) + (q & 3);
                    unsigned long long k = ((unsigned long long)ord[q] << 32)
                                         | (unsigned)(NPTS - 1 - idx);
                    if (k == win) mask &= ~(1u << q);
                }
            }
            __syncthreads();
        }
    }
}

// wdiff[o][c] = W[o][C+c] - W[o][c]   (W is O x 2C)
__global__ void k_wdiff(const float* __restrict__ W, int O, int C) {
    int i = blockIdx.x*blockDim.x + threadIdx.x;
    if (i >= O*C) return;
    int o = i / C, c = i % C;
    g_wdiff[i] = W[(size_t)o*2*C + C + c] - W[(size_t)o*2*C + c];
}

// Fused point GEMMs: u[M][O] = F * Wa^T (Wa = W[:, :C], ld 2C)
//                    v[M][O] = F * wdiff^T (ld C)
// 64x64 tile, 4x4 micro, shared A-tile.
__global__ void k_gemm_uv(const float* __restrict__ F, const float* __restrict__ W,
                          int O, int C) {
    int m0 = blockIdx.y*64, o0 = blockIdx.x*64;
    __shared__ float As[16][68];
    __shared__ float W1s[16][68];
    __shared__ float W2s[16][68];
    int tid = threadIdx.x;
    float accU[4][4], accV[4][4];
    #pragma unroll
    for (int i = 0; i < 4; i++)
        #pragma unroll
        for (int j = 0; j < 4; j++) { accU[i][j] = 0.f; accV[i][j] = 0.f; }

    for (int k0 = 0; k0 < C; k0 += 16) {
        int r = tid >> 4, c = tid & 15;
        #pragma unroll
        for (int it = 0; it < 4; it++) {
            int row = r + it*16;
            int kk = k0 + c;
            bool ok = (kk < C);
            As [c][row] = ok ? F[(size_t)(m0+row)*C + kk]        : 0.f;
            W1s[c][row] = ok ? W[(size_t)(o0+row)*2*C + kk]      : 0.f;
            W2s[c][row] = ok ? g_wdiff[(size_t)(o0+row)*C + kk]  : 0.f;
        }
        __syncthreads();
        int ti = tid & 15, tj = tid >> 4;
        #pragma unroll
        for (int k = 0; k < 16; k++) {
            float a[4], w1[4], w2[4];
            #pragma unroll
            for (int u = 0; u < 4; u++) {
                a[u]  = As [k][tj*4+u];
                w1[u] = W1s[k][ti*4+u];
                w2[u] = W2s[k][ti*4+u];
            }
            #pragma unroll
            for (int i = 0; i < 4; i++)
                #pragma unroll
                for (int j = 0; j < 4; j++) {
                    accU[i][j] += a[i]*w1[j];
                    accV[i][j] += a[i]*w2[j];
                }
        }
        __syncthreads();
    }
    int ti = tid & 15, tj = tid >> 4;
    #pragma unroll
    for (int i = 0; i < 4; i++) {
        int m = m0 + tj*4 + i;
        float4 vu = make_float4(accU[i][0], accU[i][1], accU[i][2], accU[i][3]);
        float4 vv = make_float4(accV[i][0], accV[i][1], accV[i][2], accV[i][3]);
        *(float4*)&g_u[(size_t)m*O + o0 + ti*4] = vu;
        *(float4*)&g_v[(size_t)m*O + o0 + ti*4] = vv;
    }
}

// per (b,n): pre[o] = v[o] + max_k u[idx_k][o]; partial per-channel sum/sumsq.
// 256 threads, 256/O points per block.
__global__ void k_gather(int O, float* __restrict__ pre) {
    int local = threadIdx.x / O;
    int o = threadIdx.x % O;
    int bn = blockIdx.x * (256 / O) + local;
    int b = bn >> 12;
    float vv = g_v[(size_t)bn*O + o];
    const int* idxp = &g_idx[bn*KNN];
    float mx = -3.4e38f, s = 0.f, ss = 0.f;
    #pragma unroll
    for (int k = 0; k < KNN; k++) {
        int nb = __ldg(&idxp[k]);
        float h = g_u[((size_t)(b*NPTS + nb))*O + o] + vv;
        mx = fmaxf(mx, h); s += h; ss += h*h;
    }
    pre[(size_t)bn*O + o] = mx;
    g_ps [(size_t)bn*O + o] = s;
    g_pss[(size_t)bn*O + o] = ss;
}

// deterministic reduction of partials -> g_sums/g_sumsq
__global__ void k_redstats(int nPart, int O) {
    int o = blockIdx.x, tid = threadIdx.x;
    float s = 0.f, ss = 0.f;
    for (int i = tid; i < nPart; i += 256) {
        s  += g_ps [(size_t)i*O + o];
        ss += g_pss[(size_t)i*O + o];
    }
    __shared__ float rs[256], rss[256];
    rs[tid] = s; rss[tid] = ss;
    __syncthreads();
    for (int st = 128; st > 0; st >>= 1) {
        if (tid < st) { rs[tid] += rs[tid+st]; rss[tid] += rss[tid+st]; }
        __syncthreads();
    }
    if (tid == 0) { g_sums[o] = rs[0]; g_sumsq[o] = rss[0]; }
}

// in-place affine-BN + leaky on max-pooled features
__global__ void k_finalize(const float* __restrict__ g, const float* __restrict__ bp,
                           float* __restrict__ buf, int O, float invCnt) {
    int i = blockIdx.x*blockDim.x + threadIdx.x;
    if (i >= BN_*O) return;
    int o = i % O;
    float mean = g_sums[o]*invCnt;
    float var  = g_sumsq[o]*invCnt - mean*mean;
    float sc = g[o]*rsqrtf(var + EPSV);
    float sh = bp[o] - mean*sc;
    float y = sc*buf[i] + sh;
    buf[i] = (y > 0.f) ? y : SLOPE*y;
}

// concat-space row pointer: [x1(64) | x2(64) | x3(128) | x4(256)]
// 8-wide k-chunks (k0 % 8 == 0) never cross buffer boundaries.
__device__ __forceinline__ const float* catA_ptr(int m, int k0) {
    if (k0 < 64)  return &g_x1[(size_t)m*64  + k0];
    if (k0 < 128) return &g_x2[(size_t)m*64  + (k0 - 64)];
    if (k0 < 256) return &g_x3[(size_t)m*128 + (k0 - 128)];
    return &g_x4[(size_t)m*256 + (k0 - 256)];
}

// Final GEMM: g_h[M][1024] = cat[M][512] * W5[1024][512]^T
// 256x128 tile, 16x8 micro, double-buffered, compute-bound.
__global__ void __launch_bounds__(256, 1)
k_gemm_final(const float* __restrict__ W) {
    int o0 = blockIdx.x*128, m0 = blockIdx.y*256;
    __shared__ float As[2][8][260];
    __shared__ float Ws[2][8][132];
    int tid = threadIdx.x;

    float acc[16][8];
    #pragma unroll
    for (int i = 0; i < 16; i++)
        #pragma unroll
        for (int j = 0; j < 8; j++) acc[i][j] = 0.f;

    int wrow = tid >> 1, wh = (tid & 1) * 4;

    // prologue (k0 = 0)
    {
        const float* ap = catA_ptr(m0 + tid, 0);
        float4 a0 = *(const float4*)&ap[0];
        float4 a1 = *(const float4*)&ap[4];
        As[0][0][tid] = a0.x; As[0][1][tid] = a0.y;
        As[0][2][tid] = a0.z; As[0][3][tid] = a0.w;
        As[0][4][tid] = a1.x; As[0][5][tid] = a1.y;
        As[0][6][tid] = a1.z; As[0][7][tid] = a1.w;
        float4 wv = *(const float4*)&W[(size_t)(o0+wrow)*512 + wh];
        Ws[0][wh+0][wrow] = wv.x; Ws[0][wh+1][wrow] = wv.y;
        Ws[0][wh+2][wrow] = wv.z; Ws[0][wh+3][wrow] = wv.w;
    }
    __syncthreads();

    int ti = tid & 15, tj = tid >> 4;   // ti -> o (8 each), tj -> m (16 each)
    for (int it = 0; it < 64; it++) {
        int cur = it & 1, nxt = cur ^ 1;
        if (it + 1 < 64) {
            int k0 = (it + 1) * 8;
            const float* ap = catA_ptr(m0 + tid, k0);
            float4 a0 = *(const float4*)&ap[0];
            float4 a1 = *(const float4*)&ap[4];
            As[nxt][0][tid] = a0.x; As[nxt][1][tid] = a0.y;
            As[nxt][2][tid] = a0.z; As[nxt][3][tid] = a0.w;
            As[nxt][4][tid] = a1.x; As[nxt][5][tid] = a1.y;
            As[nxt][6][tid] = a1.z; As[nxt][7][tid] = a1.w;
            float4 wv = *(const float4*)&W[(size_t)(o0+wrow)*512 + k0 + wh];
            Ws[nxt][wh+0][wrow] = wv.x; Ws[nxt][wh+1][wrow] = wv.y;
            Ws[nxt][wh+2][wrow] = wv.z; Ws[nxt][wh+3][wrow] = wv.w;
        }
        #pragma unroll
        for (int k = 0; k < 8; k++) {
            float a[16], w[8];
            #pragma unroll
            for (int u = 0; u < 16; u++) a[u] = As[cur][k][tj*16 + u];
            #pragma unroll
            for (int u = 0; u < 8; u++)  w[u] = Ws[cur][k][ti*8 + u];
            #pragma unroll
            for (int i = 0; i < 16; i++)
                #pragma unroll
                for (int j = 0; j < 8; j++) acc[i][j] += a[i]*w[j];
        }
        __syncthreads();
    }

    #pragma unroll
    for (int i = 0; i < 16; i++) {
        int m = m0 + tj*16 + i;
        float* orow = &g_h[(size_t)m*1024 + o0 + ti*8];
        float4 v0 = make_float4(acc[i][0], acc[i][1], acc[i][2], acc[i][3]);
        float4 v1 = make_float4(acc[i][4], acc[i][5], acc[i][6], acc[i][7]);
        *(float4*)&orow[0] = v0;
        *(float4*)&orow[4] = v1;
    }
}

// partial per-channel stats of g_h (8192 x 1024): 256 blocks x 32 rows
__global__ void k_hstats() {
    int r0 = blockIdx.x*32;
    float s[4] = {0,0,0,0}, ss[4] = {0,0,0,0};
    for (int r = 0; r < 32; r++) {
        const float* row = &g_h[(size_t)(r0+r)*1024];
        #pragma unroll
        for (int q = 0; q < 4; q++) {
            float v = row[threadIdx.x + q*256];
            s[q] += v; ss[q] += v*v;
        }
    }
    #pragma unroll
    for (int q = 0; q < 4; q++) {
        g_ps [(size_t)blockIdx.x*1024 + threadIdx.x + q*256] = s[q];
        g_pss[(size_t)blockIdx.x*1024 + threadIdx.x + q*256] = ss[q];
    }
}

// BN + leaky + transpose: out[b][o][n]
__global__ void k_out(const float* __restrict__ g5, const float* __restrict__ b5,
                      float* __restrict__ out) {
    __shared__ float t[32][33];
    int b = blockIdx.z;
    int n0 = blockIdx.x*32, o0 = blockIdx.y*32;
    for (int dy = threadIdx.y; dy < 32; dy += 8) {
        int n = n0 + dy;
        t[dy][threadIdx.x] = g_h[(size_t)(b*NPTS + n)*1024 + o0 + threadIdx.x];
    }
    __syncthreads();
    const float invCnt = 1.f/8192.f;
    for (int dy = threadIdx.y; dy < 32; dy += 8) {
        int o = o0 + dy, n = n0 + threadIdx.x;
        float mean = g_sums[o]*invCnt;
        float var  = g_sumsq[o]*invCnt - mean*mean;
        float sc = g5[o]*rsqrtf(var + EPSV);
        float sh = b5[o] - mean*sc;
        float hv = t[threadIdx.x][dy];
        float y = sc*hv + sh;
        out[((size_t)b*1024 + o)*NPTS + n] = (y > 0.f) ? y : SLOPE*y;
    }
}

// ---------------- host launch ----------------

static void run_layer(const float* F, int C, const float* W, const float* g,
                      const float* bp, int O, float* outbuf) {
    k_sqnorm<<<(BN_+255)/256, 256>>>(F, C);
    k_dist_sym2<<<dim3(NPTS/128, NPTS/256, BATCH), 256>>>(F, C);
    k_topk<<<BN_, 256>>>();
    k_wdiff<<<(O*C + 255)/256, 256>>>(W, O, C);
    k_gemm_uv<<<dim3(O/64, BN_/64), 256>>>(F, W, O, C);
    k_gather<<<BN_/(256/O), 256>>>(O, outbuf);
    k_redstats<<<O, 256>>>(BN_, O);
    k_finalize<<<(BN_*O + 255)/256, 256>>>(g, bp, outbuf, O, 1.f/CNT_EDGE);
}

extern "C" void kernel_launch(void* const* d_in, const int* in_sizes, int n_in,
                              void* d_out, int out_size) {
    const float* x  = (const float*)d_in[0];
    const float* W1 = (const float*)d_in[1];
    const float* g1 = (const float*)d_in[2];
    const float* b1 = (const float*)d_in[3];
    const float* W2 = (const float*)d_in[4];
    const float* g2 = (const float*)d_in[5];
    const float* b2 = (const float*)d_in[6];
    const float* W3 = (const float*)d_in[7];
    const float* g3 = (const float*)d_in[8];
    const float* b3 = (const float*)d_in[9];
    const float* W4 = (const float*)d_in[10];
    const float* g4 = (const float*)d_in[11];
    const float* b4 = (const float*)d_in[12];
    const float* W5 = (const float*)d_in[13];
    const float* g5 = (const float*)d_in[14];
    const float* b5 = (const float*)d_in[15];
    float* out = (float*)d_out;

    float *p_xb, *p_x1, *p_x2, *p_x3, *p_x4;
    cudaGetSymbolAddress((void**)&p_xb, g_xb);
    cudaGetSymbolAddress((void**)&p_x1, g_x1);
    cudaGetSymbolAddress((void**)&p_x2, g_x2);
    cudaGetSymbolAddress((void**)&p_x3, g_x3);
    cudaGetSymbolAddress((void**)&p_x4, g_x4);

    k_transpose_x<<<(BN_+255)/256, 256>>>(x);

    run_layer(p_xb, 3,   W1, g1, b1, 64,  p_x1);
    run_layer(p_x1, 64,  W2, g2, b2, 64,  p_x2);
    run_layer(p_x2, 64,  W3, g3, b3, 128, p_x3);
    run_layer(p_x3, 128, W4, g4, b4, 256, p_x4);

    k_gemm_final<<<dim3(1024/128, BN_/256), 256>>>(W5);
    k_hstats<<<256, 256>>>();
    k_redstats<<<1024, 256>>>(256, 1024);
    k_out<<<dim3(NPTS/32, 1024/32, BATCH), dim3(32, 8)>>>(g5, b5, out);
}

// round 9
// speedup vs baseline: 1.0821x; 1.0821x over previous
#include <cuda_runtime.h>
#include <cstdio>

#define BATCH 2
#define NPTS  4096
#define KNN   20
#define BN_   (BATCH*NPTS)        // 8192
#define CNT_EDGE (float)(BATCH*NPTS*KNN)   // 163840
#define EPSV 1e-5f
#define SLOPE 0.2f
#define TOPK_CAP 1024

// ---------------- static scratch (no runtime alloc allowed) ----------------
__device__ float g_xb[BN_*3];
__device__ float g_x1[BN_*64];
__device__ float g_x2[BN_*64];
__device__ float g_x3[BN_*128];
__device__ float g_x4[BN_*256];
__device__ float g_sq[BN_];
__device__ float g_D[(size_t)BATCH*NPTS*NPTS];   // 134MB distance scratch
__device__ int   g_idx[BN_*KNN];
__device__ float g_u[BN_*256];
__device__ float g_v[BN_*256];
__device__ float g_cat[BN_*512];
__device__ float g_h[(size_t)BN_*1024];
__device__ float g_ps [(size_t)BN_*256];  // partial sums
__device__ float g_pss[(size_t)BN_*256];  // partial sumsq
__device__ float g_sums[1024];
__device__ float g_sumsq[1024];

// ---------------- kernels ----------------

// x (B,3,N) -> g_xb (B,N,3)
__global__ void k_transpose_x(const float* __restrict__ x) {
    int i = blockIdx.x*blockDim.x + threadIdx.x;
    if (i >= BN_) return;
    int b = i / NPTS, n = i % NPTS;
    #pragma unroll
    for (int c = 0; c < 3; c++)
        g_xb[(size_t)i*3 + c] = x[((size_t)b*3 + c)*NPTS + n];
}

// squared norms per row
__global__ void k_sqnorm(const float* __restrict__ F, int C) {
    int i = blockIdx.x*blockDim.x + threadIdx.x;
    if (i >= BN_) return;
    const float* r = F + (size_t)i*C;
    float s = 0.f;
    for (int c = 0; c < C; c++) s += r[c]*r[c];
    g_sq[i] = s;
}

// D[b][n][m] = 2*<x_n,x_m> - ||x_n||^2 - ||x_m||^2
// Symmetric: only tiles bx >= by computed; off-diagonal tiles mirrored via
// smem-staged transpose. 128x128 tile, 8x8 micro, double-buffered smem.
__global__ void k_dist_sym(const float* __restrict__ F, int C) {
    int bx = blockIdx.x, by = blockIdx.y;
    if (bx < by) return;
    int b = blockIdx.z;
    const float* Fb = F + (size_t)b*NPTS*C;
    int m0 = bx*128, n0 = by*128;

    __shared__ float As[2][8][132];
    __shared__ float Bs[2][8][132];
    __shared__ float tr[16][132];

    int tid = threadIdx.x;
    int lr = tid & 127;          // row within tile
    int lk4 = (tid >> 7) * 4;    // 0 or 4

    float acc[8][8];
    #pragma unroll
    for (int i = 0; i < 8; i++)
        #pragma unroll
        for (int j = 0; j < 8; j++) acc[i][j] = 0.f;

    int nIter = (C + 7) / 8;
    bool vec = (C % 8 == 0);

    // prologue load (buffer 0)
    if (vec) {
        float4 va = *(const float4*)&Fb[(size_t)(n0+lr)*C + lk4];
        float4 vb = *(const float4*)&Fb[(size_t)(m0+lr)*C + lk4];
        As[0][lk4+0][lr] = va.x; As[0][lk4+1][lr] = va.y;
        As[0][lk4+2][lr] = va.z; As[0][lk4+3][lr] = va.w;
        Bs[0][lk4+0][lr] = vb.x; Bs[0][lk4+1][lr] = vb.y;
        Bs[0][lk4+2][lr] = vb.z; Bs[0][lk4+3][lr] = vb.w;
    } else {
        #pragma unroll
        for (int q = 0; q < 4; q++) {
            int cc = lk4 + q;
            As[0][lk4+q][lr] = (cc < C) ? Fb[(size_t)(n0+lr)*C + cc] : 0.f;
            Bs[0][lk4+q][lr] = (cc < C) ? Fb[(size_t)(m0+lr)*C + cc] : 0.f;
        }
    }
    __syncthreads();

    int ti = tid & 15, tj = tid >> 4;   // ti -> m (fast), tj -> n
    for (int it = 0; it < nIter; it++) {
        int cur = it & 1, nxt = cur ^ 1;
        if (it + 1 < nIter) {
            int c0 = (it + 1) * 8;
            float4 va = *(const float4*)&Fb[(size_t)(n0+lr)*C + c0 + lk4];
            float4 vb = *(const float4*)&Fb[(size_t)(m0+lr)*C + c0 + lk4];
            As[nxt][lk4+0][lr] = va.x; As[nxt][lk4+1][lr] = va.y;
            As[nxt][lk4+2][lr] = va.z; As[nxt][lk4+3][lr] = va.w;
            Bs[nxt][lk4+0][lr] = vb.x; Bs[nxt][lk4+1][lr] = vb.y;
            Bs[nxt][lk4+2][lr] = vb.z; Bs[nxt][lk4+3][lr] = vb.w;
        }
        #pragma unroll
        for (int k = 0; k < 8; k++) {
            float a[8], bv[8];
            #pragma unroll
            for (int u = 0; u < 8; u++) { a[u] = As[cur][k][tj*8+u]; bv[u] = Bs[cur][k][ti*8+u]; }
            #pragma unroll
            for (int i = 0; i < 8; i++)
                #pragma unroll
                for (int j = 0; j < 8; j++) acc[i][j] += a[i]*bv[j];
        }
        __syncthreads();
    }

    // finalize distances in-register
    float sqm[8];
    #pragma unroll
    for (int j = 0; j < 8; j++) sqm[j] = g_sq[b*NPTS + m0 + ti*8 + j];
    #pragma unroll
    for (int i = 0; i < 8; i++) {
        float sqn = g_sq[b*NPTS + n0 + tj*8 + i];
        #pragma unroll
        for (int j = 0; j < 8; j++)
            acc[i][j] = 2.f*acc[i][j] - sqn - sqm[j];
    }

    // write normal tile: D[n][m]
    #pragma unroll
    for (int i = 0; i < 8; i++) {
        int n = n0 + tj*8 + i;
        float* orow = &g_D[((size_t)b*NPTS + n)*NPTS + m0 + ti*8];
        float4 v0 = make_float4(acc[i][0], acc[i][1], acc[i][2], acc[i][3]);
        float4 v1 = make_float4(acc[i][4], acc[i][5], acc[i][6], acc[i][7]);
        *(float4*)&orow[0] = v0;
        *(float4*)&orow[4] = v1;
    }

    // mirror: D[m][n] for off-diagonal tiles, staged through smem (coalesced)
    if (bx > by) {
        for (int cc = 0; cc < 8; cc++) {
            __syncthreads();
            if ((ti >> 1) == cc) {
                int rbase = (ti & 1) * 8;
                #pragma unroll
                for (int j = 0; j < 8; j++)
                    #pragma unroll
                    for (int i = 0; i < 8; i++)
                        tr[rbase + j][tj*8 + i] = acc[i][j];
            }
            __syncthreads();
            int rr = tid >> 4;           // 0..15
            int c0w = (tid & 15) * 8;    // 0..120
            int m = m0 + cc*16 + rr;
            float* dst = &g_D[((size_t)b*NPTS + m)*NPTS + n0 + c0w];
            float4 w0 = *(float4*)&tr[rr][c0w];
            float4 w1 = *(float4*)&tr[rr][c0w + 4];
            *(float4*)&dst[0] = w0;
            *(float4*)&dst[4] = w1;
        }
    }
}

__device__ __forceinline__ unsigned f2ord(float f) {
    unsigned u = __float_as_uint(f);
    return (u & 0x80000000u) ? ~u : (u | 0x80000000u);
}

// top-20 (largest values, tie -> lowest index) per distance row.
// Radix-select: single global pass, 11-bit histogram, warp-shuffle suffix
// scan (2 barriers instead of 16), candidate ranking.
__global__ void k_topk() {
    __shared__ unsigned hist[2048];
    __shared__ unsigned wsum[8];
    __shared__ int sh_bin, ccnt;
    __shared__ unsigned long long cand[TOPK_CAP];

    int bn = blockIdx.x;
    int tid = threadIdx.x;
    int lane = tid & 31, warp = tid >> 5;
    const float4* rowv = (const float4*)&g_D[(size_t)bn*NPTS];

    for (int i = tid; i < 2048; i += 256) hist[i] = 0;
    if (tid == 0) ccnt = 0;
    __syncthreads();

    // load 16 values/thread, compute ordered keys, histogram top-11 bits
    unsigned ord[16];
    #pragma unroll
    for (int q = 0; q < 4; q++) {
        float4 v = rowv[tid + q*256];
        ord[q*4+0] = f2ord(v.x);
        ord[q*4+1] = f2ord(v.y);
        ord[q*4+2] = f2ord(v.z);
        ord[q*4+3] = f2ord(v.w);
    }
    #pragma unroll
    for (int q = 0; q < 16; q++) atomicAdd(&hist[ord[q] >> 21], 1u);
    __syncthreads();

    // per-thread sum over its 8 bins
    unsigned s_local = 0;
    #pragma unroll
    for (int j = 0; j < 8; j++) s_local += hist[tid*8 + j];

    // warp-level inclusive suffix scan (higher lane = higher bins)
    unsigned s_incl = s_local;
    #pragma unroll
    for (int off = 1; off < 32; off <<= 1) {
        unsigned v = __shfl_down_sync(0xFFFFFFFFu, s_incl, off);
        if (lane + off < 32) s_incl += v;
    }
    if (lane == 0) wsum[warp] = s_incl;
    __syncthreads();

    unsigned offset = 0;
    #pragma unroll
    for (int w = 0; w < 8; w++)
        if (w > warp) offset += wsum[w];
    // cum = count of elements in bins strictly above this thread's bin range
    unsigned cum = offset + (s_incl - s_local);
    for (int j = 7; j >= 0; j--) {
        unsigned c = hist[tid*8 + j];
        if (cum < KNN && cum + c >= KNN) { sh_bin = tid*8 + j; }
        cum += c;
    }
    __syncthreads();

    int thr = sh_bin;
    // collect candidates: all elements with bin >= threshold bin
    #pragma unroll
    for (int q = 0; q < 16; q++) {
        if ((int)(ord[q] >> 21) >= thr) {
            int idx = 4*(tid + (q >> 2)*256) + (q & 3);
            int p = atomicAdd(&ccnt, 1);
            if (p < TOPK_CAP)
                cand[p] = ((unsigned long long)ord[q] << 32) | (unsigned)(NPTS - 1 - idx);
        }
    }
    __syncthreads();

    int T = ccnt;
    if (T <= TOPK_CAP) {
        // rank candidates; keys are unique (index embedded) -> deterministic
        for (int i = tid; i < T; i += 256) {
            unsigned long long ki = cand[i];
            int r = 0;
            for (int j = 0; j < T; j++) r += (cand[j] > ki);
            if (r < KNN) {
                int idx = (NPTS - 1) - (int)(unsigned)(ki & 0xFFFFFFFFull);
                g_idx[bn*KNN + r] = idx;
            }
        }
    } else {
        // fallback (degenerate): iterative in-register selection, always correct
        __shared__ unsigned long long rb[256];
        unsigned mask = 0xFFFFu;
        for (int it = 0; it < KNN; it++) {
            unsigned long long best = 0ull;
            #pragma unroll
            for (int q = 0; q < 16; q++) {
                if ((mask >> q) & 1u) {
                    int idx = 4*(tid + (q >> 2)*256) + (q & 3);
                    unsigned long long k = ((unsigned long long)ord[q] << 32)
                                         | (unsigned)(NPTS - 1 - idx);
                    if (k > best) best = k;
                }
            }
            rb[tid] = best;
            __syncthreads();
            for (int st = 128; st > 0; st >>= 1) {
                if (tid < st && rb[tid + st] > rb[tid]) rb[tid] = rb[tid + st];
                __syncthreads();
            }
            unsigned long long win = rb[0];
            if (tid == 0)
                g_idx[bn*KNN + it] = (NPTS - 1) - (int)(unsigned)(win & 0xFFFFFFFFull);
            // owner clears its bit
            #pragma unroll
            for (int q = 0; q < 16; q++) {
                if ((mask >> q) & 1u) {
                    int idx = 4*(tid + (q >> 2)*256) + (q & 3);
                    unsigned long long k = ((unsigned long long)ord[q] << 32)
                                         | (unsigned)(NPTS - 1 - idx);
                    if (k == win) mask &= ~(1u << q);
                }
            }
            __syncthreads();
        }
    }
}

// Fused point GEMMs with inline wdiff:
//   u[M][O] = F * Wa^T         (Wa = W[:, :C])
//   v[M][O] = F * (Wb - Wa)^T  (Wb = W[:, C:2C])
// 64x64 tile, 4x4 micro, shared A-tile.
__global__ void k_gemm_uv(const float* __restrict__ F, const float* __restrict__ W,
                          int O, int C) {
    int m0 = blockIdx.y*64, o0 = blockIdx.x*64;
    __shared__ float As[16][68];
    __shared__ float W1s[16][68];
    __shared__ float W2s[16][68];
    int tid = threadIdx.x;
    float accU[4][4], accV[4][4];
    #pragma unroll
    for (int i = 0; i < 4; i++)
        #pragma unroll
        for (int j = 0; j < 4; j++) { accU[i][j] = 0.f; accV[i][j] = 0.f; }

    for (int k0 = 0; k0 < C; k0 += 16) {
        int r = tid >> 4, c = tid & 15;
        #pragma unroll
        for (int it = 0; it < 4; it++) {
            int row = r + it*16;
            int kk = k0 + c;
            bool ok = (kk < C);
            float wa = ok ? W[(size_t)(o0+row)*2*C + kk]     : 0.f;
            float wb = ok ? W[(size_t)(o0+row)*2*C + C + kk] : 0.f;
            As [c][row] = ok ? F[(size_t)(m0+row)*C + kk]    : 0.f;
            W1s[c][row] = wa;
            W2s[c][row] = wb - wa;
        }
        __syncthreads();
        int ti = tid & 15, tj = tid >> 4;
        #pragma unroll
        for (int k = 0; k < 16; k++) {
            float a[4], w1[4], w2[4];
            #pragma unroll
            for (int u = 0; u < 4; u++) {
                a[u]  = As [k][tj*4+u];
                w1[u] = W1s[k][ti*4+u];
                w2[u] = W2s[k][ti*4+u];
            }
            #pragma unroll
            for (int i = 0; i < 4; i++)
                #pragma unroll
                for (int j = 0; j < 4; j++) {
                    accU[i][j] += a[i]*w1[j];
                    accV[i][j] += a[i]*w2[j];
                }
        }
        __syncthreads();
    }
    int ti = tid & 15, tj = tid >> 4;
    #pragma unroll
    for (int i = 0; i < 4; i++) {
        int m = m0 + tj*4 + i;
        float4 vu = make_float4(accU[i][0], accU[i][1], accU[i][2], accU[i][3]);
        float4 vv = make_float4(accV[i][0], accV[i][1], accV[i][2], accV[i][3]);
        *(float4*)&g_u[(size_t)m*O + o0 + ti*4] = vu;
        *(float4*)&g_v[(size_t)m*O + o0 + ti*4] = vv;
    }
}

// per (b,n): pre[o] = v[o] + max_k u[idx_k][o]; partial per-channel sum/sumsq.
// 256 threads, 256/O points per block.
__global__ void k_gather(int O, float* __restrict__ pre) {
    int local = threadIdx.x / O;
    int o = threadIdx.x % O;
    int bn = blockIdx.x * (256 / O) + local;
    int b = bn >> 12;
    float vv = g_v[(size_t)bn*O + o];
    const int* idxp = &g_idx[bn*KNN];
    float mx = -3.4e38f, s = 0.f, ss = 0.f;
    #pragma unroll
    for (int k = 0; k < KNN; k++) {
        int nb = __ldg(&idxp[k]);
        float h = g_u[((size_t)(b*NPTS + nb))*O + o] + vv;
        mx = fmaxf(mx, h); s += h; ss += h*h;
    }
    pre[(size_t)bn*O + o] = mx;
    g_ps [(size_t)bn*O + o] = s;
    g_pss[(size_t)bn*O + o] = ss;
}

// deterministic reduction of partials -> g_sums/g_sumsq
__global__ void k_redstats(int nPart, int O) {
    int o = blockIdx.x, tid = threadIdx.x;
    float s = 0.f, ss = 0.f;
    for (int i = tid; i < nPart; i += 256) {
        s  += g_ps [(size_t)i*O + o];
        ss += g_pss[(size_t)i*O + o];
    }
    __shared__ float rs[256], rss[256];
    rs[tid] = s; rss[tid] = ss;
    __syncthreads();
    for (int st = 128; st > 0; st >>= 1) {
        if (tid < st) { rs[tid] += rs[tid+st]; rss[tid] += rss[tid+st]; }
        __syncthreads();
    }
    if (tid == 0) { g_sums[o] = rs[0]; g_sumsq[o] = rss[0]; }
}

// in-place affine-BN + leaky on max-pooled features
__global__ void k_finalize(const float* __restrict__ g, const float* __restrict__ bp,
                           float* __restrict__ buf, int O, float invCnt) {
    int i = blockIdx.x*blockDim.x + threadIdx.x;
    if (i >= BN_*O) return;
    int o = i % O;
    float mean = g_sums[o]*invCnt;
    float var  = g_sumsq[o]*invCnt - mean*mean;
    float sc = g[o]*rsqrtf(var + EPSV);
    float sh = bp[o] - mean*sc;
    float y = sc*buf[i] + sh;
    buf[i] = (y > 0.f) ? y : SLOPE*y;
}

__global__ void k_concat() {
    int i = blockIdx.x*blockDim.x + threadIdx.x;
    if (i >= BN_*512) return;
    int m = i / 512, c = i % 512;
    float v;
    if (c < 64)       v = g_x1[(size_t)m*64  + c];
    else if (c < 128) v = g_x2[(size_t)m*64  + c-64];
    else if (c < 256) v = g_x3[(size_t)m*128 + c-128];
    else              v = g_x4[(size_t)m*256 + c-256];
    g_cat[i] = v;
}

// Final GEMM: g_h[M][1024] = cat[M][512] * W5[1024][512]^T
// 128x128 tile, 8x8 micro, double-buffered.
__global__ void k_gemm128(const float* __restrict__ A, const float* __restrict__ W,
                          float* __restrict__ Out, int O, int Kd, int ldw) {
    int m0 = blockIdx.y*128, o0 = blockIdx.x*128;
    __shared__ float As[2][8][132];
    __shared__ float Ws[2][8][132];
    int tid = threadIdx.x;
    int lr = tid & 127;
    int lk4 = (tid >> 7) * 4;

    float acc[8][8];
    #pragma unroll
    for (int i = 0; i < 8; i++)
        #pragma unroll
        for (int j = 0; j < 8; j++) acc[i][j] = 0.f;

    int nIter = Kd / 8;

    {
        float4 va = *(const float4*)&A[(size_t)(m0+lr)*Kd + lk4];
        float4 vw = *(const float4*)&W[(size_t)(o0+lr)*ldw + lk4];
        As[0][lk4+0][lr] = va.x; As[0][lk4+1][lr] = va.y;
        As[0][lk4+2][lr] = va.z; As[0][lk4+3][lr] = va.w;
        Ws[0][lk4+0][lr] = vw.x; Ws[0][lk4+1][lr] = vw.y;
        Ws[0][lk4+2][lr] = vw.z; Ws[0][lk4+3][lr] = vw.w;
    }
    __syncthreads();

    int ti = tid & 15, tj = tid >> 4;
    for (int it = 0; it < nIter; it++) {
        int cur = it & 1, nxt = cur ^ 1;
        if (it + 1 < nIter) {
            int k0 = (it + 1) * 8;
            float4 va = *(const float4*)&A[(size_t)(m0+lr)*Kd + k0 + lk4];
            float4 vw = *(const float4*)&W[(size_t)(o0+lr)*ldw + k0 + lk4];
            As[nxt][lk4+0][lr] = va.x; As[nxt][lk4+1][lr] = va.y;
            As[nxt][lk4+2][lr] = va.z; As[nxt][lk4+3][lr] = va.w;
            Ws[nxt][lk4+0][lr] = vw.x; Ws[nxt][lk4+1][lr] = vw.y;
            Ws[nxt][lk4+2][lr] = vw.z; Ws[nxt][lk4+3][lr] = vw.w;
        }
        #pragma unroll
        for (int k = 0; k < 8; k++) {
            float a[8], w[8];
            #pragma unroll
            for (int u = 0; u < 8; u++) { a[u] = As[cur][k][tj*8+u]; w[u] = Ws[cur][k][ti*8+u]; }
            #pragma unroll
            for (int i = 0; i < 8; i++)
                #pragma unroll
                for (int j = 0; j < 8; j++) acc[i][j] += a[i]*w[j];
        }
        __syncthreads();
    }

    #pragma unroll
    for (int i = 0; i < 8; i++) {
        int m = m0 + tj*8 + i;
        float* orow = &Out[(size_t)m*O + o0 + ti*8];
        float4 v0 = make_float4(acc[i][0], acc[i][1], acc[i][2], acc[i][3]);
        float4 v1 = make_float4(acc[i][4], acc[i][5], acc[i][6], acc[i][7]);
        *(float4*)&orow[0] = v0;
        *(float4*)&orow[4] = v1;
    }
}

// partial per-channel stats of g_h (8192 x 1024): 256 blocks x 32 rows
__global__ void k_hstats() {
    int r0 = blockIdx.x*32;
    float s[4] = {0,0,0,0}, ss[4] = {0,0,0,0};
    for (int r = 0; r < 32; r++) {
        const float* row = &g_h[(size_t)(r0+r)*1024];
        #pragma unroll
        for (int q = 0; q < 4; q++) {
            float v = row[threadIdx.x + q*256];
            s[q] += v; ss[q] += v*v;
        }
    }
    #pragma unroll
    for (int q = 0; q < 4; q++) {
        g_ps [(size_t)blockIdx.x*1024 + threadIdx.x + q*256] = s[q];
        g_pss[(size_t)blockIdx.x*1024 + threadIdx.x + q*256] = ss[q];
    }
}

// BN + leaky + transpose: out[b][o][n]
__global__ void k_out(const float* __restrict__ g5, const float* __restrict__ b5,
                      float* __restrict__ out) {
    __shared__ float t[32][33];
    int b = blockIdx.z;
    int n0 = blockIdx.x*32, o0 = blockIdx.y*32;
    for (int dy = threadIdx.y; dy < 32; dy += 8) {
        int n = n0 + dy;
        t[dy][threadIdx.x] = g_h[(size_t)(b*NPTS + n)*1024 + o0 + threadIdx.x];
    }
    __syncthreads();
    const float invCnt = 1.f/8192.f;
    for (int dy = threadIdx.y; dy < 32; dy += 8) {
        int o = o0 + dy, n = n0 + threadIdx.x;
        float mean = g_sums[o]*invCnt;
        float var  = g_sumsq[o]*invCnt - mean*mean;
        float sc = g5[o]*rsqrtf(var + EPSV);
        float sh = b5[o] - mean*sc;
        float hv = t[threadIdx.x][dy];
        float y = sc*hv + sh;
        out[((size_t)b*1024 + o)*NPTS + n] = (y > 0.f) ? y : SLOPE*y;
    }
}

// ---------------- host launch ----------------

static void run_layer(const float* F, int C, const float* W, const float* g,
                      const float* bp, int O, float* outbuf) {
    k_sqnorm<<<(BN_+255)/256, 256>>>(F, C);
    k_dist_sym<<<dim3(NPTS/128, NPTS/128, BATCH), 256>>>(F, C);
    k_topk<<<BN_, 256>>>();
    k_gemm_uv<<<dim3(O/64, BN_/64), 256>>>(F, W, O, C);
    k_gather<<<BN_/(256/O), 256>>>(O, outbuf);
    k_redstats<<<O, 256>>>(BN_, O);
    k_finalize<<<(BN_*O + 255)/256, 256>>>(g, bp, outbuf, O, 1.f/CNT_EDGE);
}

extern "C" void kernel_launch(void* const* d_in, const int* in_sizes, int n_in,
                              void* d_out, int out_size) {
    const float* x  = (const float*)d_in[0];
    const float* W1 = (const float*)d_in[1];
    const float* g1 = (const float*)d_in[2];
    const float* b1 = (const float*)d_in[3];
    const float* W2 = (const float*)d_in[4];
    const float* g2 = (const float*)d_in[5];
    const float* b2 = (const float*)d_in[6];
    const float* W3 = (const float*)d_in[7];
    const float* g3 = (const float*)d_in[8];
    const float* b3 = (const float*)d_in[9];
    const float* W4 = (const float*)d_in[10];
    const float* g4 = (const float*)d_in[11];
    const float* b4 = (const float*)d_in[12];
    const float* W5 = (const float*)d_in[13];
    const float* g5 = (const float*)d_in[14];
    const float* b5 = (const float*)d_in[15];
    float* out = (float*)d_out;

    float *p_xb, *p_x1, *p_x2, *p_x3, *p_x4, *p_cat, *p_h;
    cudaGetSymbolAddress((void**)&p_xb,  g_xb);
    cudaGetSymbolAddress((void**)&p_x1,  g_x1);
    cudaGetSymbolAddress((void**)&p_x2,  g_x2);
    cudaGetSymbolAddress((void**)&p_x3,  g_x3);
    cudaGetSymbolAddress((void**)&p_x4,  g_x4);
    cudaGetSymbolAddress((void**)&p_cat, g_cat);
    cudaGetSymbolAddress((void**)&p_h,   g_h);

    k_transpose_x<<<(BN_+255)/256, 256>>>(x);

    run_layer(p_xb, 3,   W1, g1, b1, 64,  p_x1);
    run_layer(p_x1, 64,  W2, g2, b2, 64,  p_x2);
    run_layer(p_x2, 64,  W3, g3, b3, 128, p_x3);
    run_layer(p_x3, 128, W4, g4, b4, 256, p_x4);

    k_concat<<<(BN_*512 + 255)/256, 256>>>();
    k_gemm128<<<dim3(1024/128, BN_/128), 256>>>(p_cat, W5, p_h, 1024, 512, 512);
    k_hstats<<<256, 256>>>();
    k_redstats<<<1024, 256>>>(256, 1024);
    k_out<<<dim3(NPTS/32, 1024/32, BATCH), dim3(32, 8)>>>(g5, b5, out);
}

// round 12
// speedup vs baseline: 1.1211x; 1.0361x over previous
#include <cuda_runtime.h>
#include <cstdio>

#define BATCH 2
#define NPTS  4096
#define KNN   20
#define BN_   (BATCH*NPTS)        // 8192
#define CNT_EDGE (float)(BATCH*NPTS*KNN)   // 163840
#define EPSV 1e-5f
#define SLOPE 0.2f
#define TOPK_CAP 1024

// ---------------- static scratch (no runtime alloc allowed) ----------------
__device__ float g_xb[BN_*3];
__device__ float g_x1[BN_*64];
__device__ float g_x2[BN_*64];
__device__ float g_x3[BN_*128];
__device__ float g_x4[BN_*256];
__device__ float g_sq[BN_];
__device__ float g_D[(size_t)BATCH*NPTS*NPTS];   // 134MB distance scratch
__device__ int   g_idx[BN_*KNN];
__device__ float g_u[BN_*256];
__device__ float g_v[BN_*256];
__device__ float g_h[(size_t)BN_*1024];
__device__ float g_ps [(size_t)BN_*256];  // partial sums
__device__ float g_pss[(size_t)BN_*256];  // partial sumsq
__device__ float g_sums[1024];
__device__ float g_sumsq[1024];

// ---------------- kernels ----------------

// x (B,3,N) -> g_xb (B,N,3)
__global__ void k_transpose_x(const float* __restrict__ x) {
    int i = blockIdx.x*blockDim.x + threadIdx.x;
    if (i >= BN_) return;
    int b = i / NPTS, n = i % NPTS;
    #pragma unroll
    for (int c = 0; c < 3; c++)
        g_xb[(size_t)i*3 + c] = x[((size_t)b*3 + c)*NPTS + n];
}

// squared norms per row
__global__ void k_sqnorm(const float* __restrict__ F, int C) {
    int i = blockIdx.x*blockDim.x + threadIdx.x;
    if (i >= BN_) return;
    const float* r = F + (size_t)i*C;
    float s = 0.f;
    for (int c = 0; c < C; c++) s += r[c]*r[c];
    g_sq[i] = s;
}

// D[b][n][m] = 2*<x_n,x_m> - ||x_n||^2 - ||x_m||^2
// Symmetric: only tiles bx >= by computed; off-diagonal tiles mirrored via
// smem-staged transpose. 128x128 tile, 8x8 micro, double-buffered smem.
// fp32 SIMT on purpose: distances feed top-k selection against an fp32
// reference with dense near-ties; any lower-precision path flips them.
__global__ void k_dist_sym(const float* __restrict__ F, int C) {
    int bx = blockIdx.x, by = blockIdx.y;
    if (bx < by) return;
    int b = blockIdx.z;
    const float* Fb = F + (size_t)b*NPTS*C;
    int m0 = bx*128, n0 = by*128;

    __shared__ float As[2][8][132];
    __shared__ float Bs[2][8][132];
    __shared__ float tr[16][132];

    int tid = threadIdx.x;
    int lr = tid & 127;          // row within tile
    int lk4 = (tid >> 7) * 4;    // 0 or 4

    float acc[8][8];
    #pragma unroll
    for (int i = 0; i < 8; i++)
        #pragma unroll
        for (int j = 0; j < 8; j++) acc[i][j] = 0.f;

    int nIter = (C + 7) / 8;
    bool vec = (C % 8 == 0);

    // prologue load (buffer 0)
    if (vec) {
        float4 va = *(const float4*)&Fb[(size_t)(n0+lr)*C + lk4];
        float4 vb = *(const float4*)&Fb[(size_t)(m0+lr)*C + lk4];
        As[0][lk4+0][lr] = va.x; As[0][lk4+1][lr] = va.y;
        As[0][lk4+2][lr] = va.z; As[0][lk4+3][lr] = va.w;
        Bs[0][lk4+0][lr] = vb.x; Bs[0][lk4+1][lr] = vb.y;
        Bs[0][lk4+2][lr] = vb.z; Bs[0][lk4+3][lr] = vb.w;
    } else {
        #pragma unroll
        for (int q = 0; q < 4; q++) {
            int cc = lk4 + q;
            As[0][lk4+q][lr] = (cc < C) ? Fb[(size_t)(n0+lr)*C + cc] : 0.f;
            Bs[0][lk4+q][lr] = (cc < C) ? Fb[(size_t)(m0+lr)*C + cc] : 0.f;
        }
    }
    __syncthreads();

    int ti = tid & 15, tj = tid >> 4;   // ti -> m (fast), tj -> n
    for (int it = 0; it < nIter; it++) {
        int cur = it & 1, nxt = cur ^ 1;
        if (it + 1 < nIter) {
            int c0 = (it + 1) * 8;
            float4 va = *(const float4*)&Fb[(size_t)(n0+lr)*C + c0 + lk4];
            float4 vb = *(const float4*)&Fb[(size_t)(m0+lr)*C + c0 + lk4];
            As[nxt][lk4+0][lr] = va.x; As[nxt][lk4+1][lr] = va.y;
            As[nxt][lk4+2][lr] = va.z; As[nxt][lk4+3][lr] = va.w;
            Bs[nxt][lk4+0][lr] = vb.x; Bs[nxt][lk4+1][lr] = vb.y;
            Bs[nxt][lk4+2][lr] = vb.z; Bs[nxt][lk4+3][lr] = vb.w;
        }
        #pragma unroll
        for (int k = 0; k < 8; k++) {
            float a[8], bv[8];
            #pragma unroll
            for (int u = 0; u < 8; u++) { a[u] = As[cur][k][tj*8+u]; bv[u] = Bs[cur][k][ti*8+u]; }
            #pragma unroll
            for (int i = 0; i < 8; i++)
                #pragma unroll
                for (int j = 0; j < 8; j++) acc[i][j] += a[i]*bv[j];
        }
        __syncthreads();
    }

    // finalize distances in-register
    float sqm[8];
    #pragma unroll
    for (int j = 0; j < 8; j++) sqm[j] = g_sq[b*NPTS + m0 + ti*8 + j];
    #pragma unroll
    for (int i = 0; i < 8; i++) {
        float sqn = g_sq[b*NPTS + n0 + tj*8 + i];
        #pragma unroll
        for (int j = 0; j < 8; j++)
            acc[i][j] = 2.f*acc[i][j] - sqn - sqm[j];
    }

    // write normal tile: D[n][m]
    #pragma unroll
    for (int i = 0; i < 8; i++) {
        int n = n0 + tj*8 + i;
        float* orow = &g_D[((size_t)b*NPTS + n)*NPTS + m0 + ti*8];
        float4 v0 = make_float4(acc[i][0], acc[i][1], acc[i][2], acc[i][3]);
        float4 v1 = make_float4(acc[i][4], acc[i][5], acc[i][6], acc[i][7]);
        *(float4*)&orow[0] = v0;
        *(float4*)&orow[4] = v1;
    }

    // mirror: D[m][n] for off-diagonal tiles, staged through smem (coalesced)
    if (bx > by) {
        for (int cc = 0; cc < 8; cc++) {
            __syncthreads();
            if ((ti >> 1) == cc) {
                int rbase = (ti & 1) * 8;
                #pragma unroll
                for (int j = 0; j < 8; j++)
                    #pragma unroll
                    for (int i = 0; i < 8; i++)
                        tr[rbase + j][tj*8 + i] = acc[i][j];
            }
            __syncthreads();
            int rr = tid >> 4;           // 0..15
            int c0w = (tid & 15) * 8;    // 0..120
            int m = m0 + cc*16 + rr;
            float* dst = &g_D[((size_t)b*NPTS + m)*NPTS + n0 + c0w];
            float4 w0 = *(float4*)&tr[rr][c0w];
            float4 w1 = *(float4*)&tr[rr][c0w + 4];
            *(float4*)&dst[0] = w0;
            *(float4*)&dst[4] = w1;
        }
    }
}

__device__ __forceinline__ unsigned f2ord(float f) {
    unsigned u = __float_as_uint(f);
    return (u & 0x80000000u) ? ~u : (u | 0x80000000u);
}

// top-20 (largest values, tie -> lowest index) per distance row.
// Radix-select: single global pass, 11-bit histogram, warp-shuffle suffix
// scan, candidate ranking.
__global__ void k_topk() {
    __shared__ unsigned hist[2048];
    __shared__ unsigned wsum[8];
    __shared__ int sh_bin, ccnt;
    __shared__ unsigned long long cand[TOPK_CAP];

    int bn = blockIdx.x;
    int tid = threadIdx.x;
    int lane = tid & 31, warp = tid >> 5;
    const float4* rowv = (const float4*)&g_D[(size_t)bn*NPTS];

    for (int i = tid; i < 2048; i += 256) hist[i] = 0;
    if (tid == 0) ccnt = 0;
    __syncthreads();

    unsigned ord[16];
    #pragma unroll
    for (int q = 0; q < 4; q++) {
        float4 v = rowv[tid + q*256];
        ord[q*4+0] = f2ord(v.x);
        ord[q*4+1] = f2ord(v.y);
        ord[q*4+2] = f2ord(v.z);
        ord[q*4+3] = f2ord(v.w);
    }
    #pragma unroll
    for (int q = 0; q < 16; q++) atomicAdd(&hist[ord[q] >> 21], 1u);
    __syncthreads();

    unsigned s_local = 0;
    #pragma unroll
    for (int j = 0; j < 8; j++) s_local += hist[tid*8 + j];

    unsigned s_incl = s_local;
    #pragma unroll
    for (int off = 1; off < 32; off <<= 1) {
        unsigned v = __shfl_down_sync(0xFFFFFFFFu, s_incl, off);
        if (lane + off < 32) s_incl += v;
    }
    if (lane == 0) wsum[warp] = s_incl;
    __syncthreads();

    unsigned offset = 0;
    #pragma unroll
    for (int w = 0; w < 8; w++)
        if (w > warp) offset += wsum[w];
    unsigned cum = offset + (s_incl - s_local);
    for (int j = 7; j >= 0; j--) {
        unsigned c = hist[tid*8 + j];
        if (cum < KNN && cum + c >= KNN) { sh_bin = tid*8 + j; }
        cum += c;
    }
    __syncthreads();

    int thr = sh_bin;
    #pragma unroll
    for (int q = 0; q < 16; q++) {
        if ((int)(ord[q] >> 21) >= thr) {
            int idx = 4*(tid + (q >> 2)*256) + (q & 3);
            int p = atomicAdd(&ccnt, 1);
            if (p < TOPK_CAP)
                cand[p] = ((unsigned long long)ord[q] << 32) | (unsigned)(NPTS - 1 - idx);
        }
    }
    __syncthreads();

    int T = ccnt;
    if (T <= TOPK_CAP) {
        for (int i = tid; i < T; i += 256) {
            unsigned long long ki = cand[i];
            int r = 0;
            for (int j = 0; j < T; j++) r += (cand[j] > ki);
            if (r < KNN) {
                int idx = (NPTS - 1) - (int)(unsigned)(ki & 0xFFFFFFFFull);
                g_idx[bn*KNN + r] = idx;
            }
        }
    } else {
        __shared__ unsigned long long rb[256];
        unsigned mask = 0xFFFFu;
        for (int it = 0; it < KNN; it++) {
            unsigned long long best = 0ull;
            #pragma unroll
            for (int q = 0; q < 16; q++) {
                if ((mask >> q) & 1u) {
                    int idx = 4*(tid + (q >> 2)*256) + (q & 3);
                    unsigned long long k = ((unsigned long long)ord[q] << 32)
                                         | (unsigned)(NPTS - 1 - idx);
                    if (k > best) best = k;
                }
            }
            rb[tid] = best;
            __syncthreads();
            for (int st = 128; st > 0; st >>= 1) {
                if (tid < st && rb[tid + st] > rb[tid]) rb[tid] = rb[tid + st];
                __syncthreads();
            }
            unsigned long long win = rb[0];
            if (tid == 0)
                g_idx[bn*KNN + it] = (NPTS - 1) - (int)(unsigned)(win & 0xFFFFFFFFull);
            #pragma unroll
            for (int q = 0; q < 16; q++) {
                if ((mask >> q) & 1u) {
                    int idx = 4*(tid + (q >> 2)*256) + (q & 3);
                    unsigned long long k = ((unsigned long long)ord[q] << 32)
                                         | (unsigned)(NPTS - 1 - idx);
                    if (k == win) mask &= ~(1u << q);
                }
            }
            __syncthreads();
        }
    }
}

// Fused point GEMMs with inline wdiff:
//   u[M][O] = F * Wa^T         (Wa = W[:, :C])
//   v[M][O] = F * (Wb - Wa)^T  (Wb = W[:, C:2C])
// 64x64 tile, 4x4 micro, shared A-tile. fp32 (feeds next layer's selection).
__global__ void k_gemm_uv(const float* __restrict__ F, const float* __restrict__ W,
                          int O, int C) {
    int m0 = blockIdx.y*64, o0 = blockIdx.x*64;
    __shared__ float As[16][68];
    __shared__ float W1s[16][68];
    __shared__ float W2s[16][68];
    int tid = threadIdx.x;
    float accU[4][4], accV[4][4];
    #pragma unroll
    for (int i = 0; i < 4; i++)
        #pragma unroll
        for (int j = 0; j < 4; j++) { accU[i][j] = 0.f; accV[i][j] = 0.f; }

    for (int k0 = 0; k0 < C; k0 += 16) {
        int r = tid >> 4, c = tid & 15;
        #pragma unroll
        for (int it = 0; it < 4; it++) {
            int row = r + it*16;
            int kk = k0 + c;
            bool ok = (kk < C);
            float wa = ok ? W[(size_t)(o0+row)*2*C + kk]     : 0.f;
            float wb = ok ? W[(size_t)(o0+row)*2*C + C + kk] : 0.f;
            As [c][row] = ok ? F[(size_t)(m0+row)*C + kk]    : 0.f;
            W1s[c][row] = wa;
            W2s[c][row] = wb - wa;
        }
        __syncthreads();
        int ti = tid & 15, tj = tid >> 4;
        #pragma unroll
        for (int k = 0; k < 16; k++) {
            float a[4], w1[4], w2[4];
            #pragma unroll
            for (int u = 0; u < 4; u++) {
                a[u]  = As [k][tj*4+u];
                w1[u] = W1s[k][ti*4+u];
                w2[u] = W2s[k][ti*4+u];
            }
            #pragma unroll
            for (int i = 0; i < 4; i++)
                #pragma unroll
                for (int j = 0; j < 4; j++) {
                    accU[i][j] += a[i]*w1[j];
                    accV[i][j] += a[i]*w2[j];
                }
        }
        __syncthreads();
    }
    int ti = tid & 15, tj = tid >> 4;
    #pragma unroll
    for (int i = 0; i < 4; i++) {
        int m = m0 + tj*4 + i;
        float4 vu = make_float4(accU[i][0], accU[i][1], accU[i][2], accU[i][3]);
        float4 vv = make_float4(accV[i][0], accV[i][1], accV[i][2], accV[i][3]);
        *(float4*)&g_u[(size_t)m*O + o0 + ti*4] = vu;
        *(float4*)&g_v[(size_t)m*O + o0 + ti*4] = vv;
    }
}

// per (b,n): pre[o] = v[o] + max_k u[idx_k][o]; partial per-channel sum/sumsq.
__global__ void k_gather(int O, float* __restrict__ pre) {
    int local = threadIdx.x / O;
    int o = threadIdx.x % O;
    int bn = blockIdx.x * (256 / O) + local;
    int b = bn >> 12;
    float vv = g_v[(size_t)bn*O + o];
    const int* idxp = &g_idx[bn*KNN];
    float mx = -3.4e38f, s = 0.f, ss = 0.f;
    #pragma unroll
    for (int k = 0; k < KNN; k++) {
        int nb = __ldg(&idxp[k]);
        float h = g_u[((size_t)(b*NPTS + nb))*O + o] + vv;
        mx = fmaxf(mx, h); s += h; ss += h*h;
    }
    pre[(size_t)bn*O + o] = mx;
    g_ps [(size_t)bn*O + o] = s;
    g_pss[(size_t)bn*O + o] = ss;
}

// deterministic reduction of partials -> g_sums/g_sumsq
__global__ void k_redstats(int nPart, int O) {
    int o = blockIdx.x, tid = threadIdx.x;
    float s = 0.f, ss = 0.f;
    for (int i = tid; i < nPart; i += 256) {
        s  += g_ps [(size_t)i*O + o];
        ss += g_pss[(size_t)i*O + o];
    }
    __shared__ float rs[256], rss[256];
    rs[tid] = s; rss[tid] = ss;
    __syncthreads();
    for (int st = 128; st > 0; st >>= 1) {
        if (tid < st) { rs[tid] += rs[tid+st]; rss[tid] += rss[tid+st]; }
        __syncthreads();
    }
    if (tid == 0) { g_sums[o] = rs[0]; g_sumsq[o] = rss[0]; }
}

// in-place affine-BN + leaky on max-pooled features
__global__ void k_finalize(const float* __restrict__ g, const float* __restrict__ bp,
                           float* __restrict__ buf, int O, float invCnt) {
    int i = blockIdx.x*blockDim.x + threadIdx.x;
    if (i >= BN_*O) return;
    int o = i % O;
    float mean = g_sums[o]*invCnt;
    float var  = g_sumsq[o]*invCnt - mean*mean;
    float sc = g[o]*rsqrtf(var + EPSV);
    float sh = bp[o] - mean*sc;
    float y = sc*buf[i] + sh;
    buf[i] = (y > 0.f) ? y : SLOPE*y;
}

// concat-space row pointer: [x1(64) | x2(64) | x3(128) | x4(256)]
// float4 chunks at k0 % 4 == 0 never cross buffer boundaries (64/128/256).
__device__ __forceinline__ const float* catA_ptr(int m, int k0) {
    if (k0 < 64)  return &g_x1[(size_t)m*64  + k0];
    if (k0 < 128) return &g_x2[(size_t)m*64  + (k0 - 64)];
    if (k0 < 256) return &g_x3[(size_t)m*128 + (k0 - 128)];
    return &g_x4[(size_t)m*256 + (k0 - 256)];
}

// ---------------- tensor-core final GEMM ----------------
// g_h[M][1024] = cat[M][512] * W5[1024][512]^T
// tf32 mma m16n8k8 with hi/lo 3-term split (~1e-6 relative error).
// SAFE here: output feeds only BN+leaky (smooth), no selection downstream.
// 128(m) x 128(o) block, 512 threads (16 warps, 4x4), 32x32 warp tile.

__device__ __forceinline__ unsigned cvt_tf32(float x) {
    unsigned r;
    asm("cvt.rna.tf32.f32 %0, %1;" : "=r"(r) : "f"(x));
    return r;
}

__device__ __forceinline__ void mma_tf32(float* c, const unsigned* a, const unsigned* b) {
    asm volatile(
        "mma.sync.aligned.m16n8k8.row.col.f32.tf32.tf32.f32 "
        "{%0,%1,%2,%3}, {%4,%5,%6,%7}, {%8,%9}, {%0,%1,%2,%3};\n"
        : "+f"(c[0]), "+f"(c[1]), "+f"(c[2]), "+f"(c[3])
        : "r"(a[0]), "r"(a[1]), "r"(a[2]), "r"(a[3]), "r"(b[0]), "r"(b[1]));
}

__global__ void __launch_bounds__(512, 1)
k_gemm5_tc(const float* __restrict__ W) {
    int o0 = blockIdx.x*128, m0 = blockIdx.y*128;

    // A: sm[buf*1056 + k*132 + mrow]; B(W): sm[2112 + buf*1056 + k*132 + orow]
    __shared__ float sm[4224];

    int tid = threadIdx.x;
    int lane = tid & 31, w = tid >> 5;
    int g = lane >> 2, tg = lane & 3;
    int wn = w & 3, wm = w >> 2;   // wn -> m strip (32), wm -> o strip (32)

    float acc[2][4][4];
    #pragma unroll
    for (int tn = 0; tn < 2; tn++)
        #pragma unroll
        for (int tm = 0; tm < 4; tm++)
            #pragma unroll
            for (int q = 0; q < 4; q++) acc[tn][tm][q] = 0.f;

    int lrow = tid & 127;
    int lkh  = ((tid >> 7) & 1) * 4;   // 0 or 4
    bool isA = tid < 256;
    float* ldst = isA ? sm : (sm + 2112);

    // prologue (buffer 0, k0 = 0)
    {
        const float* src = isA ? catA_ptr(m0 + lrow, lkh)
                               : &W[(size_t)(o0 + lrow)*512 + lkh];
        float4 v = *(const float4*)src;
        ldst[(lkh+0)*132 + lrow] = v.x;
        ldst[(lkh+1)*132 + lrow] = v.y;
        ldst[(lkh+2)*132 + lrow] = v.z;
        ldst[(lkh+3)*132 + lrow] = v.w;
    }
    __syncthreads();

    for (int it = 0; it < 64; it++) {
        int cur = it & 1, nxt = cur ^ 1;
        if (it + 1 < 64) {
            int k0 = (it + 1) * 8 + lkh;
            const float* src = isA ? catA_ptr(m0 + lrow, k0)
                                   : &W[(size_t)(o0 + lrow)*512 + k0];
            float4 v = *(const float4*)src;
            ldst[nxt*1056 + (lkh+0)*132 + lrow] = v.x;
            ldst[nxt*1056 + (lkh+1)*132 + lrow] = v.y;
            ldst[nxt*1056 + (lkh+2)*132 + lrow] = v.z;
            ldst[nxt*1056 + (lkh+3)*132 + lrow] = v.w;
        }

        const float* As = sm + cur*1056;
        const float* Bs = sm + 2112 + cur*1056;

        // A fragments (m16 x k8), hi/lo split
        unsigned Ahi[2][4], Alo[2][4];
        #pragma unroll
        for (int tn = 0; tn < 2; tn++) {
            int nb = wn*32 + tn*16;
            float x0 = As[tg*132     + nb + g];
            float x1 = As[tg*132     + nb + g + 8];
            float x2 = As[(tg+4)*132 + nb + g];
            float x3 = As[(tg+4)*132 + nb + g + 8];
            unsigned h0 = cvt_tf32(x0), h1 = cvt_tf32(x1);
            unsigned h2 = cvt_tf32(x2), h3 = cvt_tf32(x3);
            Ahi[tn][0] = h0; Ahi[tn][1] = h1; Ahi[tn][2] = h2; Ahi[tn][3] = h3;
            Alo[tn][0] = cvt_tf32(x0 - __uint_as_float(h0));
            Alo[tn][1] = cvt_tf32(x1 - __uint_as_float(h1));
            Alo[tn][2] = cvt_tf32(x2 - __uint_as_float(h2));
            Alo[tn][3] = cvt_tf32(x3 - __uint_as_float(h3));
        }
        // B fragments (k8 x n8), hi/lo split
        unsigned Bhi[4][2], Blo[4][2];
        #pragma unroll
        for (int tm = 0; tm < 4; tm++) {
            int ob = wm*32 + tm*8;
            float y0 = Bs[tg*132     + ob + g];
            float y1 = Bs[(tg+4)*132 + ob + g];
            unsigned h0 = cvt_tf32(y0), h1 = cvt_tf32(y1);
            Bhi[tm][0] = h0; Bhi[tm][1] = h1;
            Blo[tm][0] = cvt_tf32(y0 - __uint_as_float(h0));
            Blo[tm][1] = cvt_tf32(y1 - __uint_as_float(h1));
        }

        #pragma unroll
        for (int tn = 0; tn < 2; tn++)
            #pragma unroll
            for (int tm = 0; tm < 4; tm++) {
                mma_tf32(acc[tn][tm], Ahi[tn], Blo[tm]);
                mma_tf32(acc[tn][tm], Alo[tn], Bhi[tm]);
                mma_tf32(acc[tn][tm], Ahi[tn], Bhi[tm]);
            }
        __syncthreads();
    }

    // epilogue: write g_h
    #pragma unroll
    for (int tn = 0; tn < 2; tn++) {
        int nb = wn*32 + tn*16;
        #pragma unroll
        for (int tm = 0; tm < 4; tm++) {
            int ob = wm*32 + tm*8;
            float* a = acc[tn][tm];
            float* r0 = &g_h[(size_t)(m0 + nb + g    )*1024 + o0 + ob + 2*tg];
            float* r1 = &g_h[(size_t)(m0 + nb + g + 8)*1024 + o0 + ob + 2*tg];
            *(float2*)r0 = make_float2(a[0], a[1]);
            *(float2*)r1 = make_float2(a[2], a[3]);
        }
    }
}

// partial per-channel stats of g_h (8192 x 1024): 256 blocks x 32 rows
__global__ void k_hstats() {
    int r0 = blockIdx.x*32;
    float s[4] = {0,0,0,0}, ss[4] = {0,0,0,0};
    for (int r = 0; r < 32; r++) {
        const float* row = &g_h[(size_t)(r0+r)*1024];
        #pragma unroll
        for (int q = 0; q < 4; q++) {
            float v = row[threadIdx.x + q*256];
            s[q] += v; ss[q] += v*v;
        }
    }
    #pragma unroll
    for (int q = 0; q < 4; q++) {
        g_ps [(size_t)blockIdx.x*1024 + threadIdx.x + q*256] = s[q];
        g_pss[(size_t)blockIdx.x*1024 + threadIdx.x + q*256] = ss[q];
    }
}

// BN + leaky + transpose: out[b][o][n]
__global__ void k_out(const float* __restrict__ g5, const float* __restrict__ b5,
                      float* __restrict__ out) {
    __shared__ float t[32][33];
    int b = blockIdx.z;
    int n0 = blockIdx.x*32, o0 = blockIdx.y*32;
    for (int dy = threadIdx.y; dy < 32; dy += 8) {
        int n = n0 + dy;
        t[dy][threadIdx.x] = g_h[(size_t)(b*NPTS + n)*1024 + o0 + threadIdx.x];
    }
    __syncthreads();
    const float invCnt = 1.f/8192.f;
    for (int dy = threadIdx.y; dy < 32; dy += 8) {
        int o = o0 + dy, n = n0 + threadIdx.x;
        float mean = g_sums[o]*invCnt;
        float var  = g_sumsq[o]*invCnt - mean*mean;
        float sc = g5[o]*rsqrtf(var + EPSV);
        float sh = b5[o] - mean*sc;
        float hv = t[threadIdx.x][dy];
        float y = sc*hv + sh;
        out[((size_t)b*1024 + o)*NPTS + n] = (y > 0.f) ? y : SLOPE*y;
    }
}

// ---------------- host launch ----------------

static void run_layer(const float* F, int C, const float* W, const float* g,
                      const float* bp, int O, float* outbuf) {
    k_sqnorm<<<(BN_+255)/256, 256>>>(F, C);
    k_dist_sym<<<dim3(NPTS/128, NPTS/128, BATCH), 256>>>(F, C);
    k_topk<<<BN_, 256>>>();
    k_gemm_uv<<<dim3(O/64, BN_/64), 256>>>(F, W, O, C);
    k_gather<<<BN_/(256/O), 256>>>(O, outbuf);
    k_redstats<<<O, 256>>>(BN_, O);
    k_finalize<<<(BN_*O + 255)/256, 256>>>(g, bp, outbuf, O, 1.f/CNT_EDGE);
}

extern "C" void kernel_launch(void* const* d_in, const int* in_sizes, int n_in,
                              void* d_out, int out_size) {
    const float* x  = (const float*)d_in[0];
    const float* W1 = (const float*)d_in[1];
    const float* g1 = (const float*)d_in[2];
    const float* b1 = (const float*)d_in[3];
    const float* W2 = (const float*)d_in[4];
    const float* g2 = (const float*)d_in[5];
    const float* b2 = (const float*)d_in[6];
    const float* W3 = (const float*)d_in[7];
    const float* g3 = (const float*)d_in[8];
    const float* b3 = (const float*)d_in[9];
    const float* W4 = (const float*)d_in[10];
    const float* g4 = (const float*)d_in[11];
    const float* b4 = (const float*)d_in[12];
    const float* W5 = (const float*)d_in[13];
    const float* g5 = (const float*)d_in[14];
    const float* b5 = (const float*)d_in[15];
    float* out = (float*)d_out;

    float *p_xb, *p_x1, *p_x2, *p_x3, *p_x4;
    cudaGetSymbolAddress((void**)&p_xb, g_xb);
    cudaGetSymbolAddress((void**)&p_x1, g_x1);
    cudaGetSymbolAddress((void**)&p_x2, g_x2);
    cudaGetSymbolAddress((void**)&p_x3, g_x3);
    cudaGetSymbolAddress((void**)&p_x4, g_x4);

    k_transpose_x<<<(BN_+255)/256, 256>>>(x);

    run_layer(p_xb, 3,   W1, g1, b1, 64,  p_x1);
    run_layer(p_x1, 64,  W2, g2, b2, 64,  p_x2);
    run_layer(p_x2, 64,  W3, g3, b3, 128, p_x3);
    run_layer(p_x3, 128, W4, g4, b4, 256, p_x4);

    k_gemm5_tc<<<dim3(1024/128, BN_/128), 512>>>(W5);
    k_hstats<<<256, 256>>>();
    k_redstats<<<1024, 256>>>(256, 1024);
    k_out<<<dim3(NPTS/32, 1024/32, BATCH), dim3(32, 8)>>>(g5, b5, out);
}

// round 14
// speedup vs baseline: 1.1409x; 1.0177x over previous
#include <cuda_runtime.h>
#include <cstdio>

#define BATCH 2
#define NPTS  4096
#define KNN   20
#define BN_   (BATCH*NPTS)        // 8192
#define CNT_EDGE (float)(BATCH*NPTS*KNN)   // 163840
#define EPSV 1e-5f
#define SLOPE 0.2f
#define TOPK_CAP 1024

// ---------------- static scratch (no runtime alloc allowed) ----------------
__device__ float g_xb[BN_*3];
__device__ float g_x1[BN_*64];
__device__ float g_x2[BN_*64];
__device__ float g_x3[BN_*128];
__device__ float g_x4[BN_*256];
__device__ float g_sq[BN_];
__device__ float g_D[(size_t)BATCH*NPTS*NPTS];   // 134MB distance scratch
__device__ int   g_idx[BN_*KNN];
__device__ float g_u[BN_*256];
__device__ float g_v[BN_*256];
__device__ float g_h[(size_t)BN_*1024];
__device__ float g_ps [(size_t)BN_*256];  // partial sums
__device__ float g_pss[(size_t)BN_*256];  // partial sumsq
__device__ float g_sums[1024];
__device__ float g_sumsq[1024];

// ---------------- kernels ----------------

// x (B,3,N) -> g_xb (B,N,3)
__global__ void k_transpose_x(const float* __restrict__ x) {
    int i = blockIdx.x*blockDim.x + threadIdx.x;
    if (i >= BN_) return;
    int b = i / NPTS, n = i % NPTS;
    #pragma unroll
    for (int c = 0; c < 3; c++)
        g_xb[(size_t)i*3 + c] = x[((size_t)b*3 + c)*NPTS + n];
}

// squared norms per row
__global__ void k_sqnorm(const float* __restrict__ F, int C) {
    int i = blockIdx.x*blockDim.x + threadIdx.x;
    if (i >= BN_) return;
    const float* r = F + (size_t)i*C;
    float s = 0.f;
    for (int c = 0; c < C; c++) s += r[c]*r[c];
    g_sq[i] = s;
}

// D[b][n][m] = 2*<x_n,x_m> - ||x_n||^2 - ||x_m||^2
// Symmetric: only tiles bx >= by computed; off-diagonal tiles mirrored via
// smem-staged transpose. 128x128 tile, 8x8 micro, double-buffered smem.
// fp32 SIMT on purpose: distances feed top-k selection against an fp32
// reference with dense near-ties; any lower-precision path flips them.
__global__ void k_dist_sym(const float* __restrict__ F, int C) {
    int bx = blockIdx.x, by = blockIdx.y;
    if (bx < by) return;
    int b = blockIdx.z;
    const float* Fb = F + (size_t)b*NPTS*C;
    int m0 = bx*128, n0 = by*128;

    __shared__ float As[2][8][132];
    __shared__ float Bs[2][8][132];
    __shared__ float tr[16][132];

    int tid = threadIdx.x;
    int lr = tid & 127;          // row within tile
    int lk4 = (tid >> 7) * 4;    // 0 or 4

    float acc[8][8];
    #pragma unroll
    for (int i = 0; i < 8; i++)
        #pragma unroll
        for (int j = 0; j < 8; j++) acc[i][j] = 0.f;

    int nIter = (C + 7) / 8;
    bool vec = (C % 8 == 0);

    // prologue load (buffer 0)
    if (vec) {
        float4 va = *(const float4*)&Fb[(size_t)(n0+lr)*C + lk4];
        float4 vb = *(const float4*)&Fb[(size_t)(m0+lr)*C + lk4];
        As[0][lk4+0][lr] = va.x; As[0][lk4+1][lr] = va.y;
        As[0][lk4+2][lr] = va.z; As[0][lk4+3][lr] = va.w;
        Bs[0][lk4+0][lr] = vb.x; Bs[0][lk4+1][lr] = vb.y;
        Bs[0][lk4+2][lr] = vb.z; Bs[0][lk4+3][lr] = vb.w;
    } else {
        #pragma unroll
        for (int q = 0; q < 4; q++) {
            int cc = lk4 + q;
            As[0][lk4+q][lr] = (cc < C) ? Fb[(size_t)(n0+lr)*C + cc] : 0.f;
            Bs[0][lk4+q][lr] = (cc < C) ? Fb[(size_t)(m0+lr)*C + cc] : 0.f;
        }
    }
    __syncthreads();

    int ti = tid & 15, tj = tid >> 4;   // ti -> m (fast), tj -> n
    for (int it = 0; it < nIter; it++) {
        int cur = it & 1, nxt = cur ^ 1;
        if (it + 1 < nIter) {
            int c0 = (it + 1) * 8;
            float4 va = *(const float4*)&Fb[(size_t)(n0+lr)*C + c0 + lk4];
            float4 vb = *(const float4*)&Fb[(size_t)(m0+lr)*C + c0 + lk4];
            As[nxt][lk4+0][lr] = va.x; As[nxt][lk4+1][lr] = va.y;
            As[nxt][lk4+2][lr] = va.z; As[nxt][lk4+3][lr] = va.w;
            Bs[nxt][lk4+0][lr] = vb.x; Bs[nxt][lk4+1][lr] = vb.y;
            Bs[nxt][lk4+2][lr] = vb.z; Bs[nxt][lk4+3][lr] = vb.w;
        }
        #pragma unroll
        for (int k = 0; k < 8; k++) {
            float a[8], bv[8];
            #pragma unroll
            for (int u = 0; u < 8; u++) { a[u] = As[cur][k][tj*8+u]; bv[u] = Bs[cur][k][ti*8+u]; }
            #pragma unroll
            for (int i = 0; i < 8; i++)
                #pragma unroll
                for (int j = 0; j < 8; j++) acc[i][j] += a[i]*bv[j];
        }
        __syncthreads();
    }

    // finalize distances in-register
    float sqm[8];
    #pragma unroll
    for (int j = 0; j < 8; j++) sqm[j] = g_sq[b*NPTS + m0 + ti*8 + j];
    #pragma unroll
    for (int i = 0; i < 8; i++) {
        float sqn = g_sq[b*NPTS + n0 + tj*8 + i];
        #pragma unroll
        for (int j = 0; j < 8; j++)
            acc[i][j] = 2.f*acc[i][j] - sqn - sqm[j];
    }

    // write normal tile: D[n][m]
    #pragma unroll
    for (int i = 0; i < 8; i++) {
        int n = n0 + tj*8 + i;
        float* orow = &g_D[((size_t)b*NPTS + n)*NPTS + m0 + ti*8];
        float4 v0 = make_float4(acc[i][0], acc[i][1], acc[i][2], acc[i][3]);
        float4 v1 = make_float4(acc[i][4], acc[i][5], acc[i][6], acc[i][7]);
        *(float4*)&orow[0] = v0;
        *(float4*)&orow[4] = v1;
    }

    // mirror: D[m][n] for off-diagonal tiles, staged through smem (coalesced)
    if (bx > by) {
        for (int cc = 0; cc < 8; cc++) {
            __syncthreads();
            if ((ti >> 1) == cc) {
                int rbase = (ti & 1) * 8;
                #pragma unroll
                for (int j = 0; j < 8; j++)
                    #pragma unroll
                    for (int i = 0; i < 8; i++)
                        tr[rbase + j][tj*8 + i] = acc[i][j];
            }
            __syncthreads();
            int rr = tid >> 4;           // 0..15
            int c0w = (tid & 15) * 8;    // 0..120
            int m = m0 + cc*16 + rr;
            float* dst = &g_D[((size_t)b*NPTS + m)*NPTS + n0 + c0w];
            float4 w0 = *(float4*)&tr[rr][c0w];
            float4 w1 = *(float4*)&tr[rr][c0w + 4];
            *(float4*)&dst[0] = w0;
            *(float4*)&dst[4] = w1;
        }
    }
}

__device__ __forceinline__ unsigned f2ord(float f) {
    unsigned u = __float_as_uint(f);
    return (u & 0x80000000u) ? ~u : (u | 0x80000000u);
}

// top-20 (largest values, tie -> lowest index) per distance row.
// Radix-select: single global pass, 11-bit histogram, warp-shuffle suffix
// scan, candidate ranking. launch_bounds(256,6): latency-bound kernel,
// trade a few spilled regs for 6 blocks/SM.
__global__ void __launch_bounds__(256, 6) k_topk() {
    __shared__ unsigned hist[2048];
    __shared__ unsigned wsum[8];
    __shared__ int sh_bin, ccnt;
    __shared__ unsigned long long cand[TOPK_CAP];

    int bn = blockIdx.x;
    int tid = threadIdx.x;
    int lane = tid & 31, warp = tid >> 5;
    const float4* rowv = (const float4*)&g_D[(size_t)bn*NPTS];

    for (int i = tid; i < 2048; i += 256) hist[i] = 0;
    if (tid == 0) ccnt = 0;
    __syncthreads();

    unsigned ord[16];
    #pragma unroll
    for (int q = 0; q < 4; q++) {
        float4 v = rowv[tid + q*256];
        ord[q*4+0] = f2ord(v.x);
        ord[q*4+1] = f2ord(v.y);
        ord[q*4+2] = f2ord(v.z);
        ord[q*4+3] = f2ord(v.w);
    }
    #pragma unroll
    for (int q = 0; q < 16; q++) atomicAdd(&hist[ord[q] >> 21], 1u);
    __syncthreads();

    unsigned s_local = 0;
    #pragma unroll
    for (int j = 0; j < 8; j++) s_local += hist[tid*8 + j];

    unsigned s_incl = s_local;
    #pragma unroll
    for (int off = 1; off < 32; off <<= 1) {
        unsigned v = __shfl_down_sync(0xFFFFFFFFu, s_incl, off);
        if (lane + off < 32) s_incl += v;
    }
    if (lane == 0) wsum[warp] = s_incl;
    __syncthreads();

    unsigned offset = 0;
    #pragma unroll
    for (int w = 0; w < 8; w++)
        if (w > warp) offset += wsum[w];
    unsigned cum = offset + (s_incl - s_local);
    for (int j = 7; j >= 0; j--) {
        unsigned c = hist[tid*8 + j];
        if (cum < KNN && cum + c >= KNN) { sh_bin = tid*8 + j; }
        cum += c;
    }
    __syncthreads();

    int thr = sh_bin;
    #pragma unroll
    for (int q = 0; q < 16; q++) {
        if ((int)(ord[q] >> 21) >= thr) {
            int idx = 4*(tid + (q >> 2)*256) + (q & 3);
            int p = atomicAdd(&ccnt, 1);
            if (p < TOPK_CAP)
                cand[p] = ((unsigned long long)ord[q] << 32) | (unsigned)(NPTS - 1 - idx);
        }
    }
    __syncthreads();

    int T = ccnt;
    if (T <= TOPK_CAP) {
        for (int i = tid; i < T; i += 256) {
            unsigned long long ki = cand[i];
            int r = 0;
            for (int j = 0; j < T; j++) r += (cand[j] > ki);
            if (r < KNN) {
                int idx = (NPTS - 1) - (int)(unsigned)(ki & 0xFFFFFFFFull);
                g_idx[bn*KNN + r] = idx;
            }
        }
    } else {
        __shared__ unsigned long long rb[256];
        unsigned mask = 0xFFFFu;
        for (int it = 0; it < KNN; it++) {
            unsigned long long best = 0ull;
            #pragma unroll
            for (int q = 0; q < 16; q++) {
                if ((mask >> q) & 1u) {
                    int idx = 4*(tid + (q >> 2)*256) + (q & 3);
                    unsigned long long k = ((unsigned long long)ord[q] << 32)
                                         | (unsigned)(NPTS - 1 - idx);
                    if (k > best) best = k;
                }
            }
            rb[tid] = best;
            __syncthreads();
            for (int st = 128; st > 0; st >>= 1) {
                if (tid < st && rb[tid + st] > rb[tid]) rb[tid] = rb[tid + st];
                __syncthreads();
            }
            unsigned long long win = rb[0];
            if (tid == 0)
                g_idx[bn*KNN + it] = (NPTS - 1) - (int)(unsigned)(win & 0xFFFFFFFFull);
            #pragma unroll
            for (int q = 0; q < 16; q++) {
                if ((mask >> q) & 1u) {
                    int idx = 4*(tid + (q >> 2)*256) + (q & 3);
                    unsigned long long k = ((unsigned long long)ord[q] << 32)
                                         | (unsigned)(NPTS - 1 - idx);
                    if (k == win) mask &= ~(1u << q);
                }
            }
            __syncthreads();
        }
    }
}

// Fused point GEMMs with inline wdiff (fp32 SIMT; layers 1-3 feed the next
// layer's KNN selection, so they must stay full fp32):
//   u[M][O] = F * Wa^T, v[M][O] = F * (Wb - Wa)^T
__global__ void k_gemm_uv(const float* __restrict__ F, const float* __restrict__ W,
                          int O, int C) {
    int m0 = blockIdx.y*64, o0 = blockIdx.x*64;
    __shared__ float As[16][68];
    __shared__ float W1s[16][68];
    __shared__ float W2s[16][68];
    int tid = threadIdx.x;
    float accU[4][4], accV[4][4];
    #pragma unroll
    for (int i = 0; i < 4; i++)
        #pragma unroll
        for (int j = 0; j < 4; j++) { accU[i][j] = 0.f; accV[i][j] = 0.f; }

    for (int k0 = 0; k0 < C; k0 += 16) {
        int r = tid >> 4, c = tid & 15;
        #pragma unroll
        for (int it = 0; it < 4; it++) {
            int row = r + it*16;
            int kk = k0 + c;
            bool ok = (kk < C);
            float wa = ok ? W[(size_t)(o0+row)*2*C + kk]     : 0.f;
            float wb = ok ? W[(size_t)(o0+row)*2*C + C + kk] : 0.f;
            As [c][row] = ok ? F[(size_t)(m0+row)*C + kk]    : 0.f;
            W1s[c][row] = wa;
            W2s[c][row] = wb - wa;
        }
        __syncthreads();
        int ti = tid & 15, tj = tid >> 4;
        #pragma unroll
        for (int k = 0; k < 16; k++) {
            float a[4], w1[4], w2[4];
            #pragma unroll
            for (int u = 0; u < 4; u++) {
                a[u]  = As [k][tj*4+u];
                w1[u] = W1s[k][ti*4+u];
                w2[u] = W2s[k][ti*4+u];
            }
            #pragma unroll
            for (int i = 0; i < 4; i++)
                #pragma unroll
                for (int j = 0; j < 4; j++) {
                    accU[i][j] += a[i]*w1[j];
                    accV[i][j] += a[i]*w2[j];
                }
        }
        __syncthreads();
    }
    int ti = tid & 15, tj = tid >> 4;
    #pragma unroll
    for (int i = 0; i < 4; i++) {
        int m = m0 + tj*4 + i;
        float4 vu = make_float4(accU[i][0], accU[i][1], accU[i][2], accU[i][3]);
        float4 vv = make_float4(accV[i][0], accV[i][1], accV[i][2], accV[i][3]);
        *(float4*)&g_u[(size_t)m*O + o0 + ti*4] = vu;
        *(float4*)&g_v[(size_t)m*O + o0 + ti*4] = vv;
    }
}

// per (b,n): pre[o] = v[o] + max_k u[idx_k][o]; partial per-channel sum/sumsq.
__global__ void k_gather(int O, float* __restrict__ pre) {
    int local = threadIdx.x / O;
    int o = threadIdx.x % O;
    int bn = blockIdx.x * (256 / O) + local;
    int b = bn >> 12;
    float vv = g_v[(size_t)bn*O + o];
    const int* idxp = &g_idx[bn*KNN];
    float mx = -3.4e38f, s = 0.f, ss = 0.f;
    #pragma unroll
    for (int k = 0; k < KNN; k++) {
        int nb = __ldg(&idxp[k]);
        float h = g_u[((size_t)(b*NPTS + nb))*O + o] + vv;
        mx = fmaxf(mx, h); s += h; ss += h*h;
    }
    pre[(size_t)bn*O + o] = mx;
    g_ps [(size_t)bn*O + o] = s;
    g_pss[(size_t)bn*O + o] = ss;
}

// deterministic reduction of partials -> g_sums/g_sumsq
__global__ void k_redstats(int nPart, int O) {
    int o = blockIdx.x, tid = threadIdx.x;
    float s = 0.f, ss = 0.f;
    for (int i = tid; i < nPart; i += 256) {
        s  += g_ps [(size_t)i*O + o];
        ss += g_pss[(size_t)i*O + o];
    }
    __shared__ float rs[256], rss[256];
    rs[tid] = s; rss[tid] = ss;
    __syncthreads();
    for (int st = 128; st > 0; st >>= 1) {
        if (tid < st) { rs[tid] += rs[tid+st]; rss[tid] += rss[tid+st]; }
        __syncthreads();
    }
    if (tid == 0) { g_sums[o] = rs[0]; g_sumsq[o] = rss[0]; }
}

// in-place affine-BN + leaky on max-pooled features
__global__ void k_finalize(const float* __restrict__ g, const float* __restrict__ bp,
                           float* __restrict__ buf, int O, float invCnt) {
    int i = blockIdx.x*blockDim.x + threadIdx.x;
    if (i >= BN_*O) return;
    int o = i % O;
    float mean = g_sums[o]*invCnt;
    float var  = g_sumsq[o]*invCnt - mean*mean;
    float sc = g[o]*rsqrtf(var + EPSV);
    float sh = bp[o] - mean*sc;
    float y = sc*buf[i] + sh;
    buf[i] = (y > 0.f) ? y : SLOPE*y;
}

// concat-space row pointer: [x1(64) | x2(64) | x3(128) | x4(256)]
// float4 chunks at k0 % 4 == 0 never cross buffer boundaries (64/128/256).
__device__ __forceinline__ const float* catA_ptr(int m, int k0) {
    if (k0 < 64)  return &g_x1[(size_t)m*64  + k0];
    if (k0 < 128) return &g_x2[(size_t)m*64  + (k0 - 64)];
    if (k0 < 256) return &g_x3[(size_t)m*128 + (k0 - 128)];
    return &g_x4[(size_t)m*256 + (k0 - 256)];
}

// ---------------- tf32 tensor-core GEMM engine ----------------
// mma m16n8k8 with hi/lo 3-term split (~1e-6 relative error).
// SAFE only where output does NOT feed KNN selection (proven R11/R12).

__device__ __forceinline__ unsigned cvt_tf32(float x) {
    unsigned r;
    asm("cvt.rna.tf32.f32 %0, %1;" : "=r"(r) : "f"(x));
    return r;
}

__device__ __forceinline__ void mma_tf32(float* c, const unsigned* a, const unsigned* b) {
    asm volatile(
        "mma.sync.aligned.m16n8k8.row.col.f32.tf32.tf32.f32 "
        "{%0,%1,%2,%3}, {%4,%5,%6,%7}, {%8,%9}, {%0,%1,%2,%3};\n"
        : "+f"(c[0]), "+f"(c[1]), "+f"(c[2]), "+f"(c[3])
        : "r"(a[0]), "r"(a[1]), "r"(a[2]), "r"(a[3]), "r"(b[0]), "r"(b[1]));
}

// Final GEMM: g_h[M][1024] = cat[M][512] * W5[1024][512]^T
// 128(m) x 128(o) block, 512 threads (16 warps, 4x4), 32x32 warp tile.
__global__ void __launch_bounds__(512, 1)
k_gemm5_tc(const float* __restrict__ W) {
    int o0 = blockIdx.x*128, m0 = blockIdx.y*128;

    // A: sm[buf*1056 + k*132 + mrow]; B(W): sm[2112 + buf*1056 + k*132 + orow]
    __shared__ float sm[4224];

    int tid = threadIdx.x;
    int lane = tid & 31, w = tid >> 5;
    int g = lane >> 2, tg = lane & 3;
    int wn = w & 3, wm = w >> 2;   // wn -> m strip (32), wm -> o strip (32)

    float acc[2][4][4];
    #pragma unroll
    for (int tn = 0; tn < 2; tn++)
        #pragma unroll
        for (int tm = 0; tm < 4; tm++)
            #pragma unroll
            for (int q = 0; q < 4; q++) acc[tn][tm][q] = 0.f;

    int lrow = tid & 127;
    int lkh  = ((tid >> 7) & 1) * 4;   // 0 or 4
    bool isA = tid < 256;
    float* ldst = isA ? sm : (sm + 2112);

    // prologue (buffer 0, k0 = 0)
    {
        const float* src = isA ? catA_ptr(m0 + lrow, lkh)
                               : &W[(size_t)(o0 + lrow)*512 + lkh];
        float4 v = *(const float4*)src;
        ldst[(lkh+0)*132 + lrow] = v.x;
        ldst[(lkh+1)*132 + lrow] = v.y;
        ldst[(lkh+2)*132 + lrow] = v.z;
        ldst[(lkh+3)*132 + lrow] = v.w;
    }
    __syncthreads();

    for (int it = 0; it < 64; it++) {
        int cur = it & 1, nxt = cur ^ 1;
        if (it + 1 < 64) {
            int k0 = (it + 1) * 8 + lkh;
            const float* src = isA ? catA_ptr(m0 + lrow, k0)
                                   : &W[(size_t)(o0 + lrow)*512 + k0];
            float4 v = *(const float4*)src;
            ldst[nxt*1056 + (lkh+0)*132 + lrow] = v.x;
            ldst[nxt*1056 + (lkh+1)*132 + lrow] = v.y;
            ldst[nxt*1056 + (lkh+2)*132 + lrow] = v.z;
            ldst[nxt*1056 + (lkh+3)*132 + lrow] = v.w;
        }

        const float* As = sm + cur*1056;
        const float* Bs = sm + 2112 + cur*1056;

        unsigned Ahi[2][4], Alo[2][4];
        #pragma unroll
        for (int tn = 0; tn < 2; tn++) {
            int nb = wn*32 + tn*16;
            float x0 = As[tg*132     + nb + g];
            float x1 = As[tg*132     + nb + g + 8];
            float x2 = As[(tg+4)*132 + nb + g];
            float x3 = As[(tg+4)*132 + nb + g + 8];
            unsigned h0 = cvt_tf32(x0), h1 = cvt_tf32(x1);
            unsigned h2 = cvt_tf32(x2), h3 = cvt_tf32(x3);
            Ahi[tn][0] = h0; Ahi[tn][1] = h1; Ahi[tn][2] = h2; Ahi[tn][3] = h3;
            Alo[tn][0] = cvt_tf32(x0 - __uint_as_float(h0));
            Alo[tn][1] = cvt_tf32(x1 - __uint_as_float(h1));
            Alo[tn][2] = cvt_tf32(x2 - __uint_as_float(h2));
            Alo[tn][3] = cvt_tf32(x3 - __uint_as_float(h3));
        }
        unsigned Bhi[4][2], Blo[4][2];
        #pragma unroll
        for (int tm = 0; tm < 4; tm++) {
            int ob = wm*32 + tm*8;
            float y0 = Bs[tg*132     + ob + g];
            float y1 = Bs[(tg+4)*132 + ob + g];
            unsigned h0 = cvt_tf32(y0), h1 = cvt_tf32(y1);
            Bhi[tm][0] = h0; Bhi[tm][1] = h1;
            Blo[tm][0] = cvt_tf32(y0 - __uint_as_float(h0));
            Blo[tm][1] = cvt_tf32(y1 - __uint_as_float(h1));
        }

        #pragma unroll
        for (int tn = 0; tn < 2; tn++)
            #pragma unroll
            for (int tm = 0; tm < 4; tm++) {
                mma_tf32(acc[tn][tm], Ahi[tn], Blo[tm]);
                mma_tf32(acc[tn][tm], Alo[tn], Bhi[tm]);
                mma_tf32(acc[tn][tm], Ahi[tn], Bhi[tm]);
            }
        __syncthreads();
    }

    #pragma unroll
    for (int tn = 0; tn < 2; tn++) {
        int nb = wn*32 + tn*16;
        #pragma unroll
        for (int tm = 0; tm < 4; tm++) {
            int ob = wm*32 + tm*8;
            float* a = acc[tn][tm];
            float* r0 = &g_h[(size_t)(m0 + nb + g    )*1024 + o0 + ob + 2*tg];
            float* r1 = &g_h[(size_t)(m0 + nb + g + 8)*1024 + o0 + ob + 2*tg];
            *(float2*)r0 = make_float2(a[0], a[1]);
            *(float2*)r1 = make_float2(a[2], a[3]);
        }
    }
}

// Generic TC GEMM: Out[M][ldo] = A[M][lda] * Beff[O][C]^T
// mode 0: Beff row o = W[o*ldw + k]        (k < C)
// mode 1: Beff row o = W[o*ldw + C + k] - W[o*ldw + k]
// Requires C % 8 == 0. Layer-4 u/v only (no selection downstream).
__global__ void __launch_bounds__(512, 1)
k_gemm_tc(const float* __restrict__ A, int lda,
          const float* __restrict__ W, int ldw, int C, int mode,
          float* __restrict__ Out, int ldo) {
    int o0 = blockIdx.x*128, m0 = blockIdx.y*128;
    __shared__ float sm[4224];

    int tid = threadIdx.x;
    int lane = tid & 31, w = tid >> 5;
    int g = lane >> 2, tg = lane & 3;
    int wn = w & 3, wm = w >> 2;

    float acc[2][4][4];
    #pragma unroll
    for (int tn = 0; tn < 2; tn++)
        #pragma unroll
        for (int tm = 0; tm < 4; tm++)
            #pragma unroll
            for (int q = 0; q < 4; q++) acc[tn][tm][q] = 0.f;

    int lrow = tid & 127;
    int lkh  = ((tid >> 7) & 1) * 4;
    bool isA = tid < 256;
    float* ldst = isA ? sm : (sm + 2112);

    // prologue (buffer 0, k0 = 0)
    {
        float4 v;
        if (isA) {
            v = *(const float4*)&A[(size_t)(m0 + lrow)*lda + lkh];
        } else {
            const float* wr = &W[(size_t)(o0 + lrow)*ldw + lkh];
            v = *(const float4*)wr;
            if (mode) {
                float4 v2 = *(const float4*)&wr[C];
                v.x = v2.x - v.x; v.y = v2.y - v.y;
                v.z = v2.z - v.z; v.w = v2.w - v.w;
            }
        }
        ldst[(lkh+0)*132 + lrow] = v.x;
        ldst[(lkh+1)*132 + lrow] = v.y;
        ldst[(lkh+2)*132 + lrow] = v.z;
        ldst[(lkh+3)*132 + lrow] = v.w;
    }
    __syncthreads();

    int nIter = C / 8;
    for (int it = 0; it < nIter; it++) {
        int cur = it & 1, nxt = cur ^ 1;
        if (it + 1 < nIter) {
            int k0 = (it + 1) * 8 + lkh;
            float4 v;
            if (isA) {
                v = *(const float4*)&A[(size_t)(m0 + lrow)*lda + k0];
            } else {
                const float* wr = &W[(size_t)(o0 + lrow)*ldw + k0];
                v = *(const float4*)wr;
                if (mode) {
                    float4 v2 = *(const float4*)&wr[C];
                    v.x = v2.x - v.x; v.y = v2.y - v.y;
                    v.z = v2.z - v.z; v.w = v2.w - v.w;
                }
            }
            ldst[nxt*1056 + (lkh+0)*132 + lrow] = v.x;
            ldst[nxt*1056 + (lkh+1)*132 + lrow] = v.y;
            ldst[nxt*1056 + (lkh+2)*132 + lrow] = v.z;
            ldst[nxt*1056 + (lkh+3)*132 + lrow] = v.w;
        }

        const float* As = sm + cur*1056;
        const float* Bs = sm + 2112 + cur*1056;

        unsigned Ahi[2][4], Alo[2][4];
        #pragma unroll
        for (int tn = 0; tn < 2; tn++) {
            int nb = wn*32 + tn*16;
            float x0 = As[tg*132     + nb + g];
            float x1 = As[tg*132     + nb + g + 8];
            float x2 = As[(tg+4)*132 + nb + g];
            float x3 = As[(tg+4)*132 + nb + g + 8];
            unsigned h0 = cvt_tf32(x0), h1 = cvt_tf32(x1);
            unsigned h2 = cvt_tf32(x2), h3 = cvt_tf32(x3);
            Ahi[tn][0] = h0; Ahi[tn][1] = h1; Ahi[tn][2] = h2; Ahi[tn][3] = h3;
            Alo[tn][0] = cvt_tf32(x0 - __uint_as_float(h0));
            Alo[tn][1] = cvt_tf32(x1 - __uint_as_float(h1));
            Alo[tn][2] = cvt_tf32(x2 - __uint_as_float(h2));
            Alo[tn][3] = cvt_tf32(x3 - __uint_as_float(h3));
        }
        unsigned Bhi[4][2], Blo[4][2];
        #pragma unroll
        for (int tm = 0; tm < 4; tm++) {
            int ob = wm*32 + tm*8;
            float y0 = Bs[tg*132     + ob + g];
            float y1 = Bs[(tg+4)*132 + ob + g];
            unsigned h0 = cvt_tf32(y0), h1 = cvt_tf32(y1);
            Bhi[tm][0] = h0; Bhi[tm][1] = h1;
            Blo[tm][0] = cvt_tf32(y0 - __uint_as_float(h0));
            Blo[tm][1] = cvt_tf32(y1 - __uint_as_float(h1));
        }

        #pragma unroll
        for (int tn = 0; tn < 2; tn++)
            #pragma unroll
            for (int tm = 0; tm < 4; tm++) {
                mma_tf32(acc[tn][tm], Ahi[tn], Blo[tm]);
                mma_tf32(acc[tn][tm], Alo[tn], Bhi[tm]);
                mma_tf32(acc[tn][tm], Ahi[tn], Bhi[tm]);
            }
        __syncthreads();
    }

    #pragma unroll
    for (int tn = 0; tn < 2; tn++) {
        int nb = wn*32 + tn*16;
        #pragma unroll
        for (int tm = 0; tm < 4; tm++) {
            int ob = wm*32 + tm*8;
            float* a = acc[tn][tm];
            float* r0 = &Out[(size_t)(m0 + nb + g    )*ldo + o0 + ob + 2*tg];
            float* r1 = &Out[(size_t)(m0 + nb + g + 8)*ldo + o0 + ob + 2*tg];
            *(float2*)r0 = make_float2(a[0], a[1]);
            *(float2*)r1 = make_float2(a[2], a[3]);
        }
    }
}

// partial per-channel stats of g_h (8192 x 1024): 256 blocks x 32 rows
__global__ void k_hstats() {
    int r0 = blockIdx.x*32;
    float s[4] = {0,0,0,0}, ss[4] = {0,0,0,0};
    for (int r = 0; r < 32; r++) {
        const float* row = &g_h[(size_t)(r0+r)*1024];
        #pragma unroll
        for (int q = 0; q < 4; q++) {
            float v = row[threadIdx.x + q*256];
            s[q] += v; ss[q] += v*v;
        }
    }
    #pragma unroll
    for (int q = 0; q < 4; q++) {
        g_ps [(size_t)blockIdx.x*1024 + threadIdx.x + q*256] = s[q];
        g_pss[(size_t)blockIdx.x*1024 + threadIdx.x + q*256] = ss[q];
    }
}

// BN + leaky + transpose: out[b][o][n]
__global__ void k_out(const float* __restrict__ g5, const float* __restrict__ b5,
                      float* __restrict__ out) {
    __shared__ float t[32][33];
    int b = blockIdx.z;
    int n0 = blockIdx.x*32, o0 = blockIdx.y*32;
    for (int dy = threadIdx.y; dy < 32; dy += 8) {
        int n = n0 + dy;
        t[dy][threadIdx.x] = g_h[(size_t)(b*NPTS + n)*1024 + o0 + threadIdx.x];
    }
    __syncthreads();
    const float invCnt = 1.f/8192.f;
    for (int dy = threadIdx.y; dy < 32; dy += 8) {
        int o = o0 + dy, n = n0 + threadIdx.x;
        float mean = g_sums[o]*invCnt;
        float var  = g_sumsq[o]*invCnt - mean*mean;
        float sc = g5[o]*rsqrtf(var + EPSV);
        float sh = b5[o] - mean*sc;
        float hv = t[threadIdx.x][dy];
        float y = sc*hv + sh;
        out[((size_t)b*1024 + o)*NPTS + n] = (y > 0.f) ? y : SLOPE*y;
    }
}

// ---------------- host launch ----------------

static void run_layer(const float* F, int C, const float* W, const float* g,
                      const float* bp, int O, float* outbuf,
                      float* p_u, float* p_v, bool tc_uv) {
    k_sqnorm<<<(BN_+255)/256, 256>>>(F, C);
    k_dist_sym<<<dim3(NPTS/128, NPTS/128, BATCH), 256>>>(F, C);
    k_topk<<<BN_, 256>>>();
    if (tc_uv) {
        // tf32 TC path: safe only when this layer's output feeds no selection
        k_gemm_tc<<<dim3(O/128, BN_/128), 512>>>(F, C, W, 2*C, C, 0, p_u, O);
        k_gemm_tc<<<dim3(O/128, BN_/128), 512>>>(F, C, W, 2*C, C, 1, p_v, O);
    } else {
        k_gemm_uv<<<dim3(O/64, BN_/64), 256>>>(F, W, O, C);
    }
    k_gather<<<BN_/(256/O), 256>>>(O, outbuf);
    k_redstats<<<O, 256>>>(BN_, O);
    k_finalize<<<(BN_*O + 255)/256, 256>>>(g, bp, outbuf, O, 1.f/CNT_EDGE);
}

extern "C" void kernel_launch(void* const* d_in, const int* in_sizes, int n_in,
                              void* d_out, int out_size) {
    const float* x  = (const float*)d_in[0];
    const float* W1 = (const float*)d_in[1];
    const float* g1 = (const float*)d_in[2];
    const float* b1 = (const float*)d_in[3];
    const float* W2 = (const float*)d_in[4];
    const float* g2 = (const float*)d_in[5];
    const float* b2 = (const float*)d_in[6];
    const float* W3 = (const float*)d_in[7];
    const float* g3 = (const float*)d_in[8];
    const float* b3 = (const float*)d_in[9];
    const float* W4 = (const float*)d_in[10];
    const float* g4 = (const float*)d_in[11];
    const float* b4 = (const float*)d_in[12];
    const float* W5 = (const float*)d_in[13];
    const float* g5 = (const float*)d_in[14];
    const float* b5 = (const float*)d_in[15];
    float* out = (float*)d_out;

    float *p_xb, *p_x1, *p_x2, *p_x3, *p_x4, *p_u, *p_v;
    cudaGetSymbolAddress((void**)&p_xb, g_xb);
    cudaGetSymbolAddress((void**)&p_x1, g_x1);
    cudaGetSymbolAddress((void**)&p_x2, g_x2);
    cudaGetSymbolAddress((void**)&p_x3, g_x3);
    cudaGetSymbolAddress((void**)&p_x4, g_x4);
    cudaGetSymbolAddress((void**)&p_u,  g_u);
    cudaGetSymbolAddress((void**)&p_v,  g_v);

    k_transpose_x<<<(BN_+255)/256, 256>>>(x);

    run_layer(p_xb, 3,   W1, g1, b1, 64,  p_x1, p_u, p_v, false);
    run_layer(p_x1, 64,  W2, g2, b2, 64,  p_x2, p_u, p_v, false);
    run_layer(p_x2, 64,  W3, g3, b3, 128, p_x3, p_u, p_v, false);
    run_layer(p_x3, 128, W4, g4, b4, 256, p_x4, p_u, p_v, true);

    k_gemm5_tc<<<dim3(1024/128, BN_/128), 512>>>(W5);
    k_hstats<<<256, 256>>>();
    k_redstats<<<1024, 256>>>(256, 1024);
    k_out<<<dim3(NPTS/32, 1024/32, BATCH), dim3(32, 8)>>>(g5, b5, out);
}